// round 1
// baseline (speedup 1.0000x reference)
#include <cuda_runtime.h>
#include <math_constants.h>

#define B_ 128
#define T_ 512
#define D_ 400
#define V_ 1024
#define A_ 128

// Scratch (no allocations allowed in kernel_launch)
__device__ float g_hW[B_ * T_];   // hW[b,t] = H[b,t,:] . W_score
__device__ float g_q[B_ * D_];    // q_acts[b,d]

// ---------------------------------------------------------------------------
// Kernel 1: hW[b,t] = dot(H[b,t,:], W)   (one warp per (b,t))
// ---------------------------------------------------------------------------
__global__ __launch_bounds__(256) void hw_kernel(const float* __restrict__ H,
                                                 const float* __restrict__ W) {
    __shared__ float sW[D_];
    for (int d = threadIdx.x; d < D_; d += 256) sW[d] = W[d];
    __syncthreads();
    int warp = threadIdx.x >> 5, lane = threadIdx.x & 31;
    int idx = blockIdx.x * 8 + warp;          // flat (b*T + t)
    const float* row = H + (size_t)idx * D_;
    float s = 0.f;
    for (int d = lane; d < D_; d += 32) s += row[d] * sW[d];
#pragma unroll
    for (int o = 16; o; o >>= 1) s += __shfl_xor_sync(0xffffffffu, s, o);
    if (lane == 0) g_hW[idx] = s;
}

// ---------------------------------------------------------------------------
// Kernel 2: fused scores GEMM + masked online softmax + weighted sum.
// Per CTA: batch b, 128 v-rows. Tile 128(v) x 128(t), K=400 in steps of 8.
// 256 threads = 16x16, each owns an 8x8 microtile.
// y_utts[b,v] = (sum_t e^{s-m} * hW[b,t]) / (sum_t e^{s-m}) + b_score
// ---------------------------------------------------------------------------
__global__ __launch_bounds__(256) void fused_kernel(const float* __restrict__ H,
                                                    const float* __restrict__ vals,
                                                    const int* __restrict__ lens,
                                                    const float* __restrict__ b_score,
                                                    float* __restrict__ y_utts) {
    __shared__ float As[8][128];   // vals tile, k-major
    __shared__ float Bs[8][128];   // H tile transposed, k-major
    __shared__ float hs[128];      // hW slice for this t-block

    const int b  = blockIdx.y;
    const int v0 = blockIdx.x * 128;
    const int tid = threadIdx.x;
    const int tx = tid & 15;       // t direction
    const int ty = tid >> 4;       // v direction
    const int len_b = lens[b];
    const float bsc = b_score[0];
    const float* Hb = H + (size_t)b * T_ * D_;

    float run_m[8], run_l[8], run_w[8];
#pragma unroll
    for (int i = 0; i < 8; i++) { run_m[i] = -CUDART_INF_F; run_l[i] = 0.f; run_w[i] = 0.f; }

    for (int t0 = 0; t0 < T_; t0 += 128) {
        __syncthreads();                         // protect previous hs reads
        if (tid < 128) hs[tid] = g_hW[b * T_ + t0 + tid];

        float acc[8][8];
#pragma unroll
        for (int i = 0; i < 8; i++)
#pragma unroll
            for (int j = 0; j < 8; j++) acc[i][j] = 0.f;

        for (int k0 = 0; k0 < D_; k0 += 8) {
            __syncthreads();                     // previous compute done
            {
                const int r = tid >> 1;
                const int c = (tid & 1) << 2;
                float4 av = *(const float4*)(vals + (size_t)(v0 + r) * D_ + k0 + c);
                As[c + 0][r] = av.x; As[c + 1][r] = av.y;
                As[c + 2][r] = av.z; As[c + 3][r] = av.w;
                float4 hv = *(const float4*)(Hb + (size_t)(t0 + r) * D_ + k0 + c);
                Bs[c + 0][r] = hv.x; Bs[c + 1][r] = hv.y;
                Bs[c + 2][r] = hv.z; Bs[c + 3][r] = hv.w;
            }
            __syncthreads();
#pragma unroll
            for (int kk = 0; kk < 8; kk++) {
                float a[8], bb[8];
#pragma unroll
                for (int i = 0; i < 8; i++) a[i]  = As[kk][ty * 8 + i];
#pragma unroll
                for (int j = 0; j < 8; j++) bb[j] = Bs[kk][tx * 8 + j];
#pragma unroll
                for (int i = 0; i < 8; i++)
#pragma unroll
                    for (int j = 0; j < 8; j++)
                        acc[i][j] = fmaf(a[i], bb[j], acc[i][j]);
            }
        }

        // ---- mask + online softmax update (row = v, reduce across 16 x-lanes)
        const int tj0 = t0 + tx * 8;
#pragma unroll
        for (int j = 0; j < 8; j++) {
            if (tj0 + j >= len_b) {
#pragma unroll
                for (int i = 0; i < 8; i++) acc[i][j] = -CUDART_INF_F;
            }
        }
#pragma unroll
        for (int i = 0; i < 8; i++) {
            float m = acc[i][0];
#pragma unroll
            for (int j = 1; j < 8; j++) m = fmaxf(m, acc[i][j]);
#pragma unroll
            for (int o = 8; o; o >>= 1)
                m = fmaxf(m, __shfl_xor_sync(0xffffffffu, m, o, 16));

            const float nm = fmaxf(run_m[i], m);         // finite after block 0
            const float scale = __expf(run_m[i] - nm);   // exp(-inf)=0 on first block
            float ls = 0.f, ws = 0.f;
#pragma unroll
            for (int j = 0; j < 8; j++) {
                float e = __expf(acc[i][j] - nm);        // masked -> exp(-inf)=0
                ls += e;
                ws += e * hs[tx * 8 + j];
            }
#pragma unroll
            for (int o = 8; o; o >>= 1) {
                ls += __shfl_xor_sync(0xffffffffu, ls, o, 16);
                ws += __shfl_xor_sync(0xffffffffu, ws, o, 16);
            }
            run_l[i] = run_l[i] * scale + ls;
            run_w[i] = run_w[i] * scale + ws;
            run_m[i] = nm;
        }
    }

    if (tx == 0) {
#pragma unroll
        for (int i = 0; i < 8; i++) {
            int v = v0 + ty * 8 + i;
            y_utts[b * V_ + v] = run_w[i] / run_l[i] + bsc;
        }
    }
}

// ---------------------------------------------------------------------------
// Kernel 3: acts path part 1: s2 -> softmax -> q_acts[b,:]
// One CTA per batch, 128 threads (thread a owns s2[b,a]).
// ---------------------------------------------------------------------------
__global__ __launch_bounds__(128) void acts_kernel(const float* __restrict__ C_acts,
                                                   const float* __restrict__ c_utt) {
    __shared__ float cu[D_];
    __shared__ float p[A_];
    __shared__ float w4[4], w4b[4];
    const int b = blockIdx.x;
    const int tid = threadIdx.x;
    const int warp = tid >> 5, lane = tid & 31;

    for (int d = tid; d < D_; d += 128) cu[d] = c_utt[b * D_ + d];
    __syncthreads();

    const float* Cb = C_acts + (size_t)b * A_ * D_;
    const float* row = Cb + (size_t)tid * D_;
    float s = 0.f;
    for (int d = 0; d < D_; d += 4) {
        float4 r = *(const float4*)(row + d);
        s += r.x * cu[d] + r.y * cu[d + 1] + r.z * cu[d + 2] + r.w * cu[d + 3];
    }
    // block max
    float m = s;
#pragma unroll
    for (int o = 16; o; o >>= 1) m = fmaxf(m, __shfl_xor_sync(0xffffffffu, m, o));
    if (lane == 0) w4[warp] = m;
    __syncthreads();
    m = fmaxf(fmaxf(w4[0], w4[1]), fmaxf(w4[2], w4[3]));

    float e = __expf(s - m);
    float sm = e;
#pragma unroll
    for (int o = 16; o; o >>= 1) sm += __shfl_xor_sync(0xffffffffu, sm, o);
    if (lane == 0) w4b[warp] = sm;
    __syncthreads();
    float tot = w4b[0] + w4b[1] + w4b[2] + w4b[3];
    p[tid] = e / tot;
    __syncthreads();

    for (int d = tid; d < D_; d += 128) {
        float q = 0.f;
        for (int a = 0; a < A_; a++) q = fmaf(p[a], Cb[(size_t)a * D_ + d], q);
        g_q[b * D_ + d] = q;
    }
}

// ---------------------------------------------------------------------------
// Kernel 4: y_acts[b,v] = dot(q_acts[b,:], vals[v,:])
// CTA = (128 v, 16 b); vals row read once, reused across 16 batches.
// ---------------------------------------------------------------------------
#define BB_ 16
__global__ __launch_bounds__(128) void yacts_kernel(const float* __restrict__ vals,
                                                    float* __restrict__ y_acts) {
    __shared__ float qs[BB_][D_];
    const int v = blockIdx.x * 128 + threadIdx.x;
    const int b0 = blockIdx.y * BB_;
    for (int f = threadIdx.x; f < BB_ * D_; f += 128)
        ((float*)qs)[f] = g_q[b0 * D_ + f];
    __syncthreads();

    float acc[BB_];
#pragma unroll
    for (int bb = 0; bb < BB_; bb++) acc[bb] = 0.f;

    const float* vrow = vals + (size_t)v * D_;
    for (int d = 0; d < D_; d += 4) {
        float4 r = *(const float4*)(vrow + d);
#pragma unroll
        for (int bb = 0; bb < BB_; bb++) {
            acc[bb] = fmaf(r.x, qs[bb][d], acc[bb]);
            acc[bb] = fmaf(r.y, qs[bb][d + 1], acc[bb]);
            acc[bb] = fmaf(r.z, qs[bb][d + 2], acc[bb]);
            acc[bb] = fmaf(r.w, qs[bb][d + 3], acc[bb]);
        }
    }
#pragma unroll
    for (int bb = 0; bb < BB_; bb++)
        y_acts[(size_t)(b0 + bb) * V_ + v] = acc[bb];
}

// ---------------------------------------------------------------------------
extern "C" void kernel_launch(void* const* d_in, const int* in_sizes, int n_in,
                              void* d_out, int out_size) {
    const float* H       = (const float*)d_in[0];  // (B,T,D)
    const float* c_utt   = (const float*)d_in[1];  // (B,D)
    const float* C_acts  = (const float*)d_in[2];  // (B,A,D)
    const float* C_vals  = (const float*)d_in[3];  // (V,1,D) == (V,D)
    const float* W       = (const float*)d_in[4];  // (1,D)
    const float* b_score = (const float*)d_in[5];  // (1,)
    const int*   lens    = (const int*)d_in[6];    // (B,)

    float* y_utts = (float*)d_out;                 // (B,V)
    float* y_acts = (float*)d_out + (size_t)B_ * V_;  // (B,V)

    hw_kernel<<<(B_ * T_) / 8, 256>>>(H, W);
    fused_kernel<<<dim3(V_ / 128, B_), 256>>>(H, C_vals, lens, b_score, y_utts);
    acts_kernel<<<B_, 128>>>(C_acts, c_utt);
    yacts_kernel<<<dim3(V_ / 128, B_ / BB_), 128>>>(C_vals, y_acts);
}

// round 3
// speedup vs baseline: 1.3235x; 1.3235x over previous
#include <cuda_runtime.h>
#include <math_constants.h>
#include <stdint.h>

#define B_ 128
#define T_ 512
#define D_ 400
#define V_ 1024
#define A_ 128

#define KC      16
#define NCHUNK  25              // 25*16 = 400 exact
#define STRIDEW 20              // smem words per row (conflict-free magic stride)
#define REG_WORDS   (128 * STRIDEW)     // one operand region (128 rows)
#define STAGE_WORDS (4 * REG_WORDS)     // Ahi, Alo, Bhi, Blo
#define SMEM_WORDS  (2 * STAGE_WORDS + 512 + 128 * 2 * 4 + 128 * 4)
#define SMEM_BYTES  (SMEM_WORDS * 4)

// -------- scratch (device globals; no runtime allocation allowed) ----------
__device__ __align__(256) float g_Hhi[B_ * T_ * D_];
__device__ __align__(256) float g_Hlo[B_ * T_ * D_];
__device__ __align__(256) float g_Vhi[V_ * D_];
__device__ __align__(256) float g_Vlo[V_ * D_];
__device__ float g_hW[B_ * T_];
__device__ float g_q[B_ * D_];

// ======================= helpers ===========================================
__device__ __forceinline__ uint32_t smem_u32(const void* p) {
    uint32_t a;
    asm("{ .reg .u64 t; cvta.to.shared.u64 t, %1; cvt.u32.u64 %0, t; }"
        : "=r"(a) : "l"(p));
    return a;
}
__device__ __forceinline__ float tf32_rna(float x) {
    uint32_t r; asm("cvt.rna.tf32.f32 %0, %1;" : "=r"(r) : "f"(x));
    return __uint_as_float(r);
}
#define CP_ASYNC16(dst, src) \
    asm volatile("cp.async.cg.shared.global [%0], [%1], 16;" \
                 :: "r"(dst), "l"(src) : "memory")
#define CP_COMMIT() asm volatile("cp.async.commit_group;" ::: "memory")
#define CP_WAIT(n)  asm volatile("cp.async.wait_group %0;" :: "n"(n) : "memory")

__device__ __forceinline__ void mma8(float d[4], const uint32_t a[4],
                                     const uint32_t b[2]) {
    asm volatile(
        "mma.sync.aligned.m16n8k8.row.col.f32.tf32.tf32.f32 "
        "{%0,%1,%2,%3}, {%4,%5,%6,%7}, {%8,%9}, {%0,%1,%2,%3};"
        : "+f"(d[0]), "+f"(d[1]), "+f"(d[2]), "+f"(d[3])
        : "r"(a[0]), "r"(a[1]), "r"(a[2]), "r"(a[3]), "r"(b[0]), "r"(b[1]));
}

// ======================= precompute: tf32 hi/lo split ======================
__global__ __launch_bounds__(256) void split_kernel(const float* __restrict__ src,
                                                    float* __restrict__ hi,
                                                    float* __restrict__ lo,
                                                    int n4) {
    int i = blockIdx.x * 256 + threadIdx.x;
    int stride = gridDim.x * 256;
    for (; i < n4; i += stride) {
        float4 x = ((const float4*)src)[i];
        float4 h, l;
        h.x = tf32_rna(x.x); l.x = x.x - h.x;
        h.y = tf32_rna(x.y); l.y = x.y - h.y;
        h.z = tf32_rna(x.z); l.z = x.z - h.z;
        h.w = tf32_rna(x.w); l.w = x.w - h.w;
        ((float4*)hi)[i] = h;
        ((float4*)lo)[i] = l;
    }
}

// ======================= hW[b,t] = H[b,t,:].W ==============================
__global__ __launch_bounds__(256) void hw_kernel(const float* __restrict__ H,
                                                 const float* __restrict__ W) {
    __shared__ float sW[D_];
    for (int d = threadIdx.x; d < D_; d += 256) sW[d] = W[d];
    __syncthreads();
    int warp = threadIdx.x >> 5, lane = threadIdx.x & 31;
    int idx = blockIdx.x * 8 + warp;
    const float* row = H + (size_t)idx * D_;
    float s = 0.f;
    for (int d = lane; d < D_; d += 32) s += row[d] * sW[d];
#pragma unroll
    for (int o = 16; o; o >>= 1) s += __shfl_xor_sync(0xffffffffu, s, o);
    if (lane == 0) g_hW[idx] = s;
}

// ======================= fused scores GEMM + softmax =======================
// CTA: batch b, 128 v-rows. 4 t-tiles of 128. 8 warps: warpM=wid&3 (32 rows),
// warpN=wid>>2 (64 cols). Warp tile 32x64 via m16n8k8, 3xTF32.
__global__ __launch_bounds__(256, 2) void fused_kernel(const int* __restrict__ lens,
                                                       const float* __restrict__ b_score,
                                                       float* __restrict__ y_utts) {
    extern __shared__ float sm[];
    float* hs = sm + 2 * STAGE_WORDS;                    // 512
    float4* part = (float4*)(hs + 512);                  // 128*2
    float4* run  = part + 128 * 2;                       // 128
    const uint32_t sbase = smem_u32(sm);
    const uint32_t* smw = (const uint32_t*)sm;

    const int tid = threadIdx.x, lane = tid & 31, wid = tid >> 5;
    const int g = lane >> 2, tig = lane & 3;
    const int warpM = wid & 3, warpN = wid >> 2;
    const int b = blockIdx.y, v0 = blockIdx.x * 128;
    const int len_b = lens[b];
    const float bsc = b_score[0];

    for (int i = tid; i < T_; i += 256) hs[i] = g_hW[b * T_ + i];
    if (tid < 128) run[tid] = make_float4(-CUDART_INF_F, 0.f, 0.f, 0.f);
    __syncthreads();

    const float* srcAh = g_Vhi + v0 * D_;
    const float* srcAl = g_Vlo + v0 * D_;

    for (int t0 = 0; t0 < T_; t0 += 128) {
        const float* srcBh = g_Hhi + (b * T_ + t0) * D_;
        const float* srcBl = g_Hlo + (b * T_ + t0) * D_;

        float acc[2][8][4];
#pragma unroll
        for (int mt = 0; mt < 2; mt++)
#pragma unroll
            for (int nt = 0; nt < 8; nt++)
#pragma unroll
                for (int r = 0; r < 4; r++) acc[mt][nt][r] = 0.f;

        // ---- cp.async staging helper (inlined twice) ----
        const int crow = tid >> 2, cq = (tid & 3) * 4;
#define COPY_CHUNK(ST, K0) do {                                                \
        int _k = (K0);                                                         \
        uint32_t _d0 = sbase + ((ST) * STAGE_WORDS + crow * STRIDEW + cq) * 4; \
        CP_ASYNC16(_d0,                    srcAh + crow * D_ + _k + cq);       \
        CP_ASYNC16(_d0 + 64 * STRIDEW * 4, srcAh + (crow + 64) * D_ + _k + cq);\
        uint32_t _d1 = _d0 + REG_WORDS * 4;                                    \
        CP_ASYNC16(_d1,                    srcAl + crow * D_ + _k + cq);       \
        CP_ASYNC16(_d1 + 64 * STRIDEW * 4, srcAl + (crow + 64) * D_ + _k + cq);\
        uint32_t _d2 = _d1 + REG_WORDS * 4;                                    \
        CP_ASYNC16(_d2,                    srcBh + crow * D_ + _k + cq);       \
        CP_ASYNC16(_d2 + 64 * STRIDEW * 4, srcBh + (crow + 64) * D_ + _k + cq);\
        uint32_t _d3 = _d2 + REG_WORDS * 4;                                    \
        CP_ASYNC16(_d3,                    srcBl + crow * D_ + _k + cq);       \
        CP_ASYNC16(_d3 + 64 * STRIDEW * 4, srcBl + (crow + 64) * D_ + _k + cq);\
    } while (0)

        COPY_CHUNK(0, 0);
        CP_COMMIT();

        for (int kc = 0; kc < NCHUNK; kc++) {
            const int st = kc & 1;
            if (kc + 1 < NCHUNK) {
                COPY_CHUNK(st ^ 1, (kc + 1) * KC);
                CP_COMMIT();
                CP_WAIT(1);
            } else {
                CP_WAIT(0);
            }
            __syncthreads();

            const uint32_t off = st * STAGE_WORDS;
#pragma unroll
            for (int s = 0; s < 2; s++) {
                const int col = s * 8 + tig;
                uint32_t ah[2][4], al[2][4], bb[8][2];
#pragma unroll
                for (int mt = 0; mt < 2; mt++) {
                    const int r0 = warpM * 32 + mt * 16 + g;
                    const uint32_t* ph = smw + off + r0 * STRIDEW + col;
                    ah[mt][0] = ph[0];
                    ah[mt][1] = ph[8 * STRIDEW];
                    ah[mt][2] = ph[4];
                    ah[mt][3] = ph[8 * STRIDEW + 4];
                    const uint32_t* pl = ph + REG_WORDS;
                    al[mt][0] = pl[0];
                    al[mt][1] = pl[8 * STRIDEW];
                    al[mt][2] = pl[4];
                    al[mt][3] = pl[8 * STRIDEW + 4];
                }
#pragma unroll
                for (int nt = 0; nt < 8; nt++) {
                    const int tr = warpN * 64 + nt * 8 + g;
                    const uint32_t* pb = smw + off + 2 * REG_WORDS + tr * STRIDEW + col;
                    bb[nt][0] = pb[0];
                    bb[nt][1] = pb[4];
                }
#pragma unroll
                for (int nt = 0; nt < 8; nt++)
#pragma unroll
                    for (int mt = 0; mt < 2; mt++) {
                        mma8(acc[mt][nt], ah[mt], bb[nt]);
                        mma8(acc[mt][nt], al[mt], bb[nt]);
                    }
#pragma unroll
                for (int nt = 0; nt < 8; nt++) {
                    const int tr = warpN * 64 + nt * 8 + g;
                    const uint32_t* pb = smw + off + 3 * REG_WORDS + tr * STRIDEW + col;
                    bb[nt][0] = pb[0];
                    bb[nt][1] = pb[4];
                }
#pragma unroll
                for (int nt = 0; nt < 8; nt++)
#pragma unroll
                    for (int mt = 0; mt < 2; mt++)
                        mma8(acc[mt][nt], ah[mt], bb[nt]);
            }
            __syncthreads();
        }

        // ---- epilogue: masked softmax partials per (row, warpN half) ----
#pragma unroll
        for (int mt = 0; mt < 2; mt++)
#pragma unroll
            for (int rh = 0; rh < 2; rh++) {
                float m = -CUDART_INF_F;
#pragma unroll
                for (int nt = 0; nt < 8; nt++)
#pragma unroll
                    for (int j2 = 0; j2 < 2; j2++) {
                        int tc = t0 + warpN * 64 + nt * 8 + 2 * tig + j2;
                        float x = acc[mt][nt][rh * 2 + j2];
                        m = fmaxf(m, tc < len_b ? x : -CUDART_INF_F);
                    }
                m = fmaxf(m, __shfl_xor_sync(0xffffffffu, m, 1));
                m = fmaxf(m, __shfl_xor_sync(0xffffffffu, m, 2));
                float l = 0.f, w = 0.f;
#pragma unroll
                for (int nt = 0; nt < 8; nt++)
#pragma unroll
                    for (int j2 = 0; j2 < 2; j2++) {
                        int tc = t0 + warpN * 64 + nt * 8 + 2 * tig + j2;
                        if (tc < len_b) {
                            float e = __expf(acc[mt][nt][rh * 2 + j2] - m);
                            l += e;
                            w += e * hs[tc];
                        }
                    }
                l += __shfl_xor_sync(0xffffffffu, l, 1);
                l += __shfl_xor_sync(0xffffffffu, l, 2);
                w += __shfl_xor_sync(0xffffffffu, w, 1);
                w += __shfl_xor_sync(0xffffffffu, w, 2);
                if (tig == 0) {
                    int row = warpM * 32 + mt * 16 + g + rh * 8;
                    part[row * 2 + warpN] = make_float4(m, l, w, 0.f);
                }
            }
        __syncthreads();
        if (tid < 128) {
            float4 r = run[tid];
            float4 p0 = part[tid * 2 + 0];
            float4 p1 = part[tid * 2 + 1];
            float nm = fmaxf(r.x, fmaxf(p0.x, p1.x));
            float er = __expf(r.x - nm);
            float e0 = __expf(p0.x - nm);
            float e1 = __expf(p1.x - nm);
            r.y = r.y * er + p0.y * e0 + p1.y * e1;
            r.z = r.z * er + p0.z * e0 + p1.z * e1;
            r.x = nm;
            run[tid] = r;
        }
        // no extra sync needed: part is rewritten only after next tile's
        // k-loop (many __syncthreads in between)
    }

    if (tid < 128)
        y_utts[b * V_ + v0 + tid] = run[tid].z / run[tid].y + bsc;
#undef COPY_CHUNK
}

// ======================= acts path =========================================
__global__ __launch_bounds__(128) void acts_kernel(const float* __restrict__ C_acts,
                                                   const float* __restrict__ c_utt) {
    __shared__ float cu[D_];
    __shared__ float p[A_];
    __shared__ float w4[4], w4b[4];
    const int b = blockIdx.x;
    const int tid = threadIdx.x;
    const int warp = tid >> 5, lane = tid & 31;

    for (int d = tid; d < D_; d += 128) cu[d] = c_utt[b * D_ + d];
    __syncthreads();

    const float* Cb = C_acts + (size_t)b * A_ * D_;
    const float* row = Cb + (size_t)tid * D_;
    float s = 0.f;
    for (int d = 0; d < D_; d += 4) {
        float4 r = *(const float4*)(row + d);
        s += r.x * cu[d] + r.y * cu[d + 1] + r.z * cu[d + 2] + r.w * cu[d + 3];
    }
    float m = s;
#pragma unroll
    for (int o = 16; o; o >>= 1) m = fmaxf(m, __shfl_xor_sync(0xffffffffu, m, o));
    if (lane == 0) w4[warp] = m;
    __syncthreads();
    m = fmaxf(fmaxf(w4[0], w4[1]), fmaxf(w4[2], w4[3]));

    float e = __expf(s - m);
    float smv = e;
#pragma unroll
    for (int o = 16; o; o >>= 1) smv += __shfl_xor_sync(0xffffffffu, smv, o);
    if (lane == 0) w4b[warp] = smv;
    __syncthreads();
    float tot = w4b[0] + w4b[1] + w4b[2] + w4b[3];
    p[tid] = e / tot;
    __syncthreads();

    for (int d = tid; d < D_; d += 128) {
        float q = 0.f;
        for (int a = 0; a < A_; a++) q = fmaf(p[a], Cb[(size_t)a * D_ + d], q);
        g_q[b * D_ + d] = q;
    }
}

// ======================= y_acts = q @ vals^T ===============================
#define BB_ 4
__global__ __launch_bounds__(128) void yacts_kernel(const float* __restrict__ vals,
                                                    float* __restrict__ y_acts) {
    __shared__ float qs[BB_][D_];
    const int v = blockIdx.x * 128 + threadIdx.x;
    const int b0 = blockIdx.y * BB_;
    for (int f = threadIdx.x; f < BB_ * D_; f += 128)
        ((float*)qs)[f] = g_q[b0 * D_ + f];
    __syncthreads();

    float acc[BB_];
#pragma unroll
    for (int bb = 0; bb < BB_; bb++) acc[bb] = 0.f;

    const float* vrow = vals + (size_t)v * D_;
    for (int d = 0; d < D_; d += 4) {
        float4 r = *(const float4*)(vrow + d);
#pragma unroll
        for (int bb = 0; bb < BB_; bb++) {
            acc[bb] = fmaf(r.x, qs[bb][d], acc[bb]);
            acc[bb] = fmaf(r.y, qs[bb][d + 1], acc[bb]);
            acc[bb] = fmaf(r.z, qs[bb][d + 2], acc[bb]);
            acc[bb] = fmaf(r.w, qs[bb][d + 3], acc[bb]);
        }
    }
#pragma unroll
    for (int bb = 0; bb < BB_; bb++)
        y_acts[(size_t)(b0 + bb) * V_ + v] = acc[bb];
}

// ===========================================================================
extern "C" void kernel_launch(void* const* d_in, const int* in_sizes, int n_in,
                              void* d_out, int out_size) {
    const float* H       = (const float*)d_in[0];
    const float* c_utt   = (const float*)d_in[1];
    const float* C_acts  = (const float*)d_in[2];
    const float* C_vals  = (const float*)d_in[3];
    const float* W       = (const float*)d_in[4];
    const float* b_score = (const float*)d_in[5];
    const int*   lens    = (const int*)d_in[6];

    float* y_utts = (float*)d_out;
    float* y_acts = (float*)d_out + (size_t)B_ * V_;

    static float* p_Hhi = nullptr;
    static float* p_Hlo = nullptr;
    static float* p_Vhi = nullptr;
    static float* p_Vlo = nullptr;
    if (!p_Hhi) {
        cudaGetSymbolAddress((void**)&p_Hhi, g_Hhi);
        cudaGetSymbolAddress((void**)&p_Hlo, g_Hlo);
        cudaGetSymbolAddress((void**)&p_Vhi, g_Vhi);
        cudaGetSymbolAddress((void**)&p_Vlo, g_Vlo);
        cudaFuncSetAttribute(fused_kernel,
                             cudaFuncAttributeMaxDynamicSharedMemorySize, SMEM_BYTES);
    }

    split_kernel<<<1024, 256>>>(H, p_Hhi, p_Hlo, B_ * T_ * D_ / 4);
    split_kernel<<<256, 256>>>(C_vals, p_Vhi, p_Vlo, V_ * D_ / 4);
    hw_kernel<<<(B_ * T_) / 8, 256>>>(H, W);
    fused_kernel<<<dim3(V_ / 128, B_), 256, SMEM_BYTES>>>(lens, b_score, y_utts);
    acts_kernel<<<B_, 128>>>(C_acts, c_utt);
    yacts_kernel<<<dim3(V_ / 128, B_ / BB_), 128>>>(C_vals, y_acts);
}

// round 4
// speedup vs baseline: 2.0011x; 1.5120x over previous
#include <cuda_runtime.h>
#include <cuda_bf16.h>
#include <math_constants.h>
#include <stdint.h>

#define B_ 128
#define T_ 512
#define D_ 400
#define V_ 1024
#define A_ 128

#define KC      16              // K elems per chunk (one m16n8k16 step)
#define NCHUNK  25              // 25*16 = 400 exact
#define STRIDEW 12              // smem words per row (8 data words + 4 pad)
#define REG_WORDS   (128 * STRIDEW)     // one operand region (128 rows)
#define STAGE_WORDS (4 * REG_WORDS)     // Ahi, Alo, Bhi, Blo
#define SMEM_WORDS  (2 * STAGE_WORDS + 512 + 128 * 2 * 4 + 128 * 4)
#define SMEM_BYTES  (SMEM_WORDS * 4)

// -------- scratch (device globals; no runtime allocation allowed) ----------
__device__ __align__(256) __nv_bfloat16 g_Hhi[B_ * T_ * D_];
__device__ __align__(256) __nv_bfloat16 g_Hlo[B_ * T_ * D_];
__device__ __align__(256) __nv_bfloat16 g_Vhi[V_ * D_];
__device__ __align__(256) __nv_bfloat16 g_Vlo[V_ * D_];
__device__ float g_hW[B_ * T_];
__device__ float g_q[B_ * D_];

// ======================= helpers ===========================================
__device__ __forceinline__ uint32_t smem_u32(const void* p) {
    uint32_t a;
    asm("{ .reg .u64 t; cvta.to.shared.u64 t, %1; cvt.u32.u64 %0, t; }"
        : "=r"(a) : "l"(p));
    return a;
}
#define CP_ASYNC16(dst, src) \
    asm volatile("cp.async.cg.shared.global [%0], [%1], 16;" \
                 :: "r"(dst), "l"(src) : "memory")
#define CP_COMMIT() asm volatile("cp.async.commit_group;" ::: "memory")
#define CP_WAIT(n)  asm volatile("cp.async.wait_group %0;" :: "n"(n) : "memory")

__device__ __forceinline__ void mma16(float d[4], const uint32_t a[4],
                                      const uint32_t b[2]) {
    asm volatile(
        "mma.sync.aligned.m16n8k16.row.col.f32.bf16.bf16.f32 "
        "{%0,%1,%2,%3}, {%4,%5,%6,%7}, {%8,%9}, {%0,%1,%2,%3};"
        : "+f"(d[0]), "+f"(d[1]), "+f"(d[2]), "+f"(d[3])
        : "r"(a[0]), "r"(a[1]), "r"(a[2]), "r"(a[3]), "r"(b[0]), "r"(b[1]));
}

// ======================= precompute: bf16 hi/lo split ======================
// Processes 8 floats per thread-iter -> one 16B store to hi and lo each.
__global__ __launch_bounds__(256) void split_kernel(const float* __restrict__ src,
                                                    __nv_bfloat16* __restrict__ hi,
                                                    __nv_bfloat16* __restrict__ lo,
                                                    int n8) {
    int i = blockIdx.x * 256 + threadIdx.x;
    int stride = gridDim.x * 256;
    for (; i < n8; i += stride) {
        const float4* s = (const float4*)src + 2 * (size_t)i;
        float4 x0 = s[0], x1 = s[1];
        float xs[8] = {x0.x, x0.y, x0.z, x0.w, x1.x, x1.y, x1.z, x1.w};
        __nv_bfloat16 h[8], l[8];
#pragma unroll
        for (int j = 0; j < 8; j++) {
            h[j] = __float2bfloat16_rn(xs[j]);
            l[j] = __float2bfloat16_rn(xs[j] - __bfloat162float(h[j]));
        }
        *(uint4*)(hi + 8 * (size_t)i) = *(const uint4*)h;
        *(uint4*)(lo + 8 * (size_t)i) = *(const uint4*)l;
    }
}

// ======================= hW[b,t] = H[b,t,:].W ==============================
__global__ __launch_bounds__(256) void hw_kernel(const float* __restrict__ H,
                                                 const float* __restrict__ W) {
    __shared__ float sW[D_];
    for (int d = threadIdx.x; d < D_; d += 256) sW[d] = W[d];
    __syncthreads();
    int warp = threadIdx.x >> 5, lane = threadIdx.x & 31;
    int idx = blockIdx.x * 8 + warp;
    const float* row = H + (size_t)idx * D_;
    float s = 0.f;
    for (int d = lane; d < D_; d += 32) s += row[d] * sW[d];
#pragma unroll
    for (int o = 16; o; o >>= 1) s += __shfl_xor_sync(0xffffffffu, s, o);
    if (lane == 0) g_hW[idx] = s;
}

// ======================= fused scores GEMM + softmax =======================
// CTA: batch b, 128 v-rows. 4 t-tiles of 128. 8 warps: warpM=wid&3 (32 rows),
// warpN=wid>>2 (64 cols). Warp tile 32x64 via m16n8k16, 3xBF16 split.
__global__ __launch_bounds__(256, 2) void fused_kernel(const int* __restrict__ lens,
                                                       const float* __restrict__ b_score,
                                                       float* __restrict__ y_utts) {
    extern __shared__ float sm[];
    float* hs = sm + 2 * STAGE_WORDS;                    // 512
    float4* part = (float4*)(hs + 512);                  // 128*2
    float4* run  = part + 128 * 2;                       // 128
    const uint32_t sbase = smem_u32(sm);
    const uint32_t* smw = (const uint32_t*)sm;

    const int tid = threadIdx.x, lane = tid & 31, wid = tid >> 5;
    const int g = lane >> 2, tig = lane & 3;
    const int warpM = wid & 3, warpN = wid >> 2;
    const int b = blockIdx.y, v0 = blockIdx.x * 128;
    const int len_b = lens[b];
    const float bsc = b_score[0];

    for (int i = tid; i < T_; i += 256) hs[i] = g_hW[b * T_ + i];
    if (tid < 128) run[tid] = make_float4(-CUDART_INF_F, 0.f, 0.f, 0.f);
    __syncthreads();

    const __nv_bfloat16* srcAh = g_Vhi + (size_t)v0 * D_;
    const __nv_bfloat16* srcAl = g_Vlo + (size_t)v0 * D_;

    // copy mapping: 2 threads per row, 16B (8 bf16) each, per region
    const int crow = tid >> 1;
    const int ch   = (tid & 1);           // half-row: 8 bf16
#define COPY_CHUNK(ST, K0) do {                                                \
        int _k = (K0) + ch * 8;                                                \
        uint32_t _d = sbase + ((ST) * STAGE_WORDS + crow * STRIDEW + ch * 4) * 4;\
        CP_ASYNC16(_d,                     srcAh + (size_t)crow * D_ + _k);    \
        CP_ASYNC16(_d + REG_WORDS * 4,     srcAl + (size_t)crow * D_ + _k);    \
        CP_ASYNC16(_d + 2 * REG_WORDS * 4, srcBh + (size_t)crow * D_ + _k);    \
        CP_ASYNC16(_d + 3 * REG_WORDS * 4, srcBl + (size_t)crow * D_ + _k);    \
    } while (0)

    for (int t0 = 0; t0 < T_; t0 += 128) {
        const __nv_bfloat16* srcBh = g_Hhi + (size_t)(b * T_ + t0) * D_;
        const __nv_bfloat16* srcBl = g_Hlo + (size_t)(b * T_ + t0) * D_;

        float acc[2][8][4];
#pragma unroll
        for (int mt = 0; mt < 2; mt++)
#pragma unroll
            for (int nt = 0; nt < 8; nt++)
#pragma unroll
                for (int r = 0; r < 4; r++) acc[mt][nt][r] = 0.f;

        COPY_CHUNK(0, 0);
        CP_COMMIT();

        for (int kc = 0; kc < NCHUNK; kc++) {
            const int st = kc & 1;
            if (kc + 1 < NCHUNK) {
                COPY_CHUNK(st ^ 1, (kc + 1) * KC);
                CP_COMMIT();
                CP_WAIT(1);
            } else {
                CP_WAIT(0);
            }
            __syncthreads();

            const uint32_t off = st * STAGE_WORDS;
            // --- A fragments (hi & lo), rows = v ---
            uint32_t ah[2][4], al[2][4], bb[8][2];
#pragma unroll
            for (int mt = 0; mt < 2; mt++) {
                const int r0 = warpM * 32 + mt * 16 + g;
                const uint32_t* ph = smw + off + r0 * STRIDEW + tig;
                ah[mt][0] = ph[0];
                ah[mt][1] = ph[8 * STRIDEW];
                ah[mt][2] = ph[4];
                ah[mt][3] = ph[8 * STRIDEW + 4];
                const uint32_t* pl = ph + REG_WORDS;
                al[mt][0] = pl[0];
                al[mt][1] = pl[8 * STRIDEW];
                al[mt][2] = pl[4];
                al[mt][3] = pl[8 * STRIDEW + 4];
            }
            // --- B hi fragments, rows = t ---
#pragma unroll
            for (int nt = 0; nt < 8; nt++) {
                const int tr = warpN * 64 + nt * 8 + g;
                const uint32_t* pb = smw + off + 2 * REG_WORDS + tr * STRIDEW + tig;
                bb[nt][0] = pb[0];
                bb[nt][1] = pb[4];
            }
#pragma unroll
            for (int nt = 0; nt < 8; nt++)
#pragma unroll
                for (int mt = 0; mt < 2; mt++) {
                    mma16(acc[mt][nt], ah[mt], bb[nt]);   // hi*hi
                    mma16(acc[mt][nt], al[mt], bb[nt]);   // lo*hi
                }
            // --- B lo fragments ---
#pragma unroll
            for (int nt = 0; nt < 8; nt++) {
                const int tr = warpN * 64 + nt * 8 + g;
                const uint32_t* pb = smw + off + 3 * REG_WORDS + tr * STRIDEW + tig;
                bb[nt][0] = pb[0];
                bb[nt][1] = pb[4];
            }
#pragma unroll
            for (int nt = 0; nt < 8; nt++)
#pragma unroll
                for (int mt = 0; mt < 2; mt++)
                    mma16(acc[mt][nt], ah[mt], bb[nt]);   // hi*lo
            __syncthreads();
        }

        // ---- epilogue: masked softmax partials per (row, warpN half) ----
#pragma unroll
        for (int mt = 0; mt < 2; mt++)
#pragma unroll
            for (int rh = 0; rh < 2; rh++) {
                float m = -CUDART_INF_F;
#pragma unroll
                for (int nt = 0; nt < 8; nt++)
#pragma unroll
                    for (int j2 = 0; j2 < 2; j2++) {
                        int tc = t0 + warpN * 64 + nt * 8 + 2 * tig + j2;
                        float x = acc[mt][nt][rh * 2 + j2];
                        m = fmaxf(m, tc < len_b ? x : -CUDART_INF_F);
                    }
                m = fmaxf(m, __shfl_xor_sync(0xffffffffu, m, 1));
                m = fmaxf(m, __shfl_xor_sync(0xffffffffu, m, 2));
                float l = 0.f, w = 0.f;
#pragma unroll
                for (int nt = 0; nt < 8; nt++)
#pragma unroll
                    for (int j2 = 0; j2 < 2; j2++) {
                        int tc = t0 + warpN * 64 + nt * 8 + 2 * tig + j2;
                        if (tc < len_b) {
                            float e = __expf(acc[mt][nt][rh * 2 + j2] - m);
                            l += e;
                            w += e * hs[tc];
                        }
                    }
                l += __shfl_xor_sync(0xffffffffu, l, 1);
                l += __shfl_xor_sync(0xffffffffu, l, 2);
                w += __shfl_xor_sync(0xffffffffu, w, 1);
                w += __shfl_xor_sync(0xffffffffu, w, 2);
                if (tig == 0) {
                    int row = warpM * 32 + mt * 16 + g + rh * 8;
                    part[row * 2 + warpN] = make_float4(m, l, w, 0.f);
                }
            }
        __syncthreads();
        if (tid < 128) {
            float4 r = run[tid];
            float4 p0 = part[tid * 2 + 0];
            float4 p1 = part[tid * 2 + 1];
            float nm = fmaxf(r.x, fmaxf(p0.x, p1.x));
            float er = __expf(r.x - nm);
            float e0 = __expf(p0.x - nm);
            float e1 = __expf(p1.x - nm);
            r.y = r.y * er + p0.y * e0 + p1.y * e1;
            r.z = r.z * er + p0.z * e0 + p1.z * e1;
            r.x = nm;
            run[tid] = r;
        }
        // part reused only after next tile's k-loop (many syncs in between)
    }

    if (tid < 128)
        y_utts[b * V_ + v0 + tid] = run[tid].z / run[tid].y + bsc;
#undef COPY_CHUNK
}

// ======================= acts path =========================================
__global__ __launch_bounds__(128) void acts_kernel(const float* __restrict__ C_acts,
                                                   const float* __restrict__ c_utt) {
    __shared__ float cu[D_];
    __shared__ float p[A_];
    __shared__ float w4[4], w4b[4];
    const int b = blockIdx.x;
    const int tid = threadIdx.x;
    const int warp = tid >> 5, lane = tid & 31;

    for (int d = tid; d < D_; d += 128) cu[d] = c_utt[b * D_ + d];
    __syncthreads();

    const float* Cb = C_acts + (size_t)b * A_ * D_;
    const float* row = Cb + (size_t)tid * D_;
    float s = 0.f;
    for (int d = 0; d < D_; d += 4) {
        float4 r = *(const float4*)(row + d);
        s += r.x * cu[d] + r.y * cu[d + 1] + r.z * cu[d + 2] + r.w * cu[d + 3];
    }
    float m = s;
#pragma unroll
    for (int o = 16; o; o >>= 1) m = fmaxf(m, __shfl_xor_sync(0xffffffffu, m, o));
    if (lane == 0) w4[warp] = m;
    __syncthreads();
    m = fmaxf(fmaxf(w4[0], w4[1]), fmaxf(w4[2], w4[3]));

    float e = __expf(s - m);
    float smv = e;
#pragma unroll
    for (int o = 16; o; o >>= 1) smv += __shfl_xor_sync(0xffffffffu, smv, o);
    if (lane == 0) w4b[warp] = smv;
    __syncthreads();
    float tot = w4b[0] + w4b[1] + w4b[2] + w4b[3];
    p[tid] = e / tot;
    __syncthreads();

    for (int d = tid; d < D_; d += 128) {
        float q = 0.f;
        for (int a = 0; a < A_; a++) q = fmaf(p[a], Cb[(size_t)a * D_ + d], q);
        g_q[b * D_ + d] = q;
    }
}

// ======================= y_acts = q @ vals^T ===============================
#define BB_ 4
__global__ __launch_bounds__(128) void yacts_kernel(const float* __restrict__ vals,
                                                    float* __restrict__ y_acts) {
    __shared__ float qs[BB_][D_];
    const int v = blockIdx.x * 128 + threadIdx.x;
    const int b0 = blockIdx.y * BB_;
    for (int f = threadIdx.x; f < BB_ * D_; f += 128)
        ((float*)qs)[f] = g_q[b0 * D_ + f];
    __syncthreads();

    float acc[BB_];
#pragma unroll
    for (int bb = 0; bb < BB_; bb++) acc[bb] = 0.f;

    const float* vrow = vals + (size_t)v * D_;
    for (int d = 0; d < D_; d += 4) {
        float4 r = *(const float4*)(vrow + d);
#pragma unroll
        for (int bb = 0; bb < BB_; bb++) {
            acc[bb] = fmaf(r.x, qs[bb][d], acc[bb]);
            acc[bb] = fmaf(r.y, qs[bb][d + 1], acc[bb]);
            acc[bb] = fmaf(r.z, qs[bb][d + 2], acc[bb]);
            acc[bb] = fmaf(r.w, qs[bb][d + 3], acc[bb]);
        }
    }
#pragma unroll
    for (int bb = 0; bb < BB_; bb++)
        y_acts[(size_t)(b0 + bb) * V_ + v] = acc[bb];
}

// ===========================================================================
extern "C" void kernel_launch(void* const* d_in, const int* in_sizes, int n_in,
                              void* d_out, int out_size) {
    const float* H       = (const float*)d_in[0];
    const float* c_utt   = (const float*)d_in[1];
    const float* C_acts  = (const float*)d_in[2];
    const float* C_vals  = (const float*)d_in[3];
    const float* W       = (const float*)d_in[4];
    const float* b_score = (const float*)d_in[5];
    const int*   lens    = (const int*)d_in[6];

    float* y_utts = (float*)d_out;
    float* y_acts = (float*)d_out + (size_t)B_ * V_;

    static __nv_bfloat16* p_Hhi = nullptr;
    static __nv_bfloat16* p_Hlo = nullptr;
    static __nv_bfloat16* p_Vhi = nullptr;
    static __nv_bfloat16* p_Vlo = nullptr;
    if (!p_Hhi) {
        cudaGetSymbolAddress((void**)&p_Hhi, g_Hhi);
        cudaGetSymbolAddress((void**)&p_Hlo, g_Hlo);
        cudaGetSymbolAddress((void**)&p_Vhi, g_Vhi);
        cudaGetSymbolAddress((void**)&p_Vlo, g_Vlo);
        cudaFuncSetAttribute(fused_kernel,
                             cudaFuncAttributeMaxDynamicSharedMemorySize, SMEM_BYTES);
    }

    split_kernel<<<1024, 256>>>(H, p_Hhi, p_Hlo, B_ * T_ * D_ / 8);
    split_kernel<<<128, 256>>>(C_vals, p_Vhi, p_Vlo, V_ * D_ / 8);
    hw_kernel<<<(B_ * T_) / 8, 256>>>(H, W);
    fused_kernel<<<dim3(V_ / 128, B_), 256, SMEM_BYTES>>>(lens, b_score, y_utts);
    acts_kernel<<<B_, 128>>>(C_acts, c_utt);
    yacts_kernel<<<dim3(V_ / 128, B_ / BB_), 128>>>(C_vals, y_acts);
}

// round 5
// speedup vs baseline: 2.5246x; 1.2616x over previous
#include <cuda_runtime.h>
#include <cuda_bf16.h>
#include <math_constants.h>
#include <stdint.h>

#define B_ 128
#define T_ 512
#define D_ 400
#define V_ 1024
#define A_ 128

#define KC      16              // K elems per chunk (one m16n8k16 step)
#define NCHUNK  25              // 25*16 = 400 exact
#define STRIDEW 12              // smem words per row (8 data + 4 pad), conflict-free
#define REG_WORDS   (128 * STRIDEW)
#define STAGE_WORDS (4 * REG_WORDS)     // Ahi, Alo, Bhi, Blo
#define SMEM_WORDS  (2 * STAGE_WORDS + 512 + 128 * 2 * 4 + 128 * 4)
#define SMEM_BYTES  (SMEM_WORDS * 4)

// -------- scratch (device globals; no runtime allocation allowed) ----------
__device__ __align__(256) __nv_bfloat16 g_Hhi[B_ * T_ * D_];
__device__ __align__(256) __nv_bfloat16 g_Hlo[B_ * T_ * D_];
__device__ __align__(256) __nv_bfloat16 g_Vhi[V_ * D_];
__device__ __align__(256) __nv_bfloat16 g_Vlo[V_ * D_];
__device__ float g_hW[B_ * T_];
__device__ float g_q[B_ * D_];

// ======================= helpers ===========================================
__device__ __forceinline__ uint32_t smem_u32(const void* p) {
    uint32_t a;
    asm("{ .reg .u64 t; cvta.to.shared.u64 t, %1; cvt.u32.u64 %0, t; }"
        : "=r"(a) : "l"(p));
    return a;
}
#define CP_ASYNC16(dst, src) \
    asm volatile("cp.async.cg.shared.global [%0], [%1], 16;" \
                 :: "r"(dst), "l"(src) : "memory")
#define CP_COMMIT() asm volatile("cp.async.commit_group;" ::: "memory")
#define CP_WAIT0()  asm volatile("cp.async.wait_group 0;" ::: "memory")

#define LDSM_X4(R, addr)                                                      \
    asm volatile("ldmatrix.sync.aligned.m8n8.x4.shared.b16 {%0,%1,%2,%3}, [%4];" \
        : "=r"((R)[0]), "=r"((R)[1]), "=r"((R)[2]), "=r"((R)[3]) : "r"(addr))

__device__ __forceinline__ void mma16(float d[4], const uint32_t a[4],
                                      const uint32_t b0, const uint32_t b1) {
    asm volatile(
        "mma.sync.aligned.m16n8k16.row.col.f32.bf16.bf16.f32 "
        "{%0,%1,%2,%3}, {%4,%5,%6,%7}, {%8,%9}, {%0,%1,%2,%3};"
        : "+f"(d[0]), "+f"(d[1]), "+f"(d[2]), "+f"(d[3])
        : "r"(a[0]), "r"(a[1]), "r"(a[2]), "r"(a[3]), "r"(b0), "r"(b1));
}

// ============ prep: H -> bf16 hi/lo split AND hW = H.W in one pass =========
// CTA 256 threads = 4 rows; 64 threads/row, thread j covers floats 8j..8j+7.
__global__ __launch_bounds__(256) void prep_h_kernel(const float* __restrict__ H,
                                                     const float* __restrict__ W) {
    __shared__ float sW[D_];
    __shared__ float red[4][2];
    for (int d = threadIdx.x; d < D_; d += 256) sW[d] = W[d];
    __syncthreads();

    const int rg = threadIdx.x >> 6;          // row group 0..3
    const int j  = threadIdx.x & 63;          // 8-float slot
    const int lane = threadIdx.x & 31;
    const size_t row = blockIdx.x * 4 + rg;
    const size_t base = row * D_ + j * 8;

    float s = 0.f;
    if (j < 50) {
        float4 x0 = *(const float4*)(H + base);
        float4 x1 = *(const float4*)(H + base + 4);
        float xs[8] = {x0.x, x0.y, x0.z, x0.w, x1.x, x1.y, x1.z, x1.w};
        __nv_bfloat16 h[8], l[8];
#pragma unroll
        for (int k = 0; k < 8; k++) {
            h[k] = __float2bfloat16_rn(xs[k]);
            l[k] = __float2bfloat16_rn(xs[k] - __bfloat162float(h[k]));
            s += xs[k] * sW[j * 8 + k];
        }
        *(uint4*)(g_Hhi + base) = *(const uint4*)h;
        *(uint4*)(g_Hlo + base) = *(const uint4*)l;
    }
#pragma unroll
    for (int o = 16; o; o >>= 1) s += __shfl_xor_sync(0xffffffffu, s, o);
    if (lane == 0) red[rg][(threadIdx.x >> 5) & 1] = s;
    __syncthreads();
    if ((threadIdx.x & 63) == 0) g_hW[row] = red[rg][0] + red[rg][1];
}

// ======================= V: bf16 hi/lo split ===============================
__global__ __launch_bounds__(256) void split_kernel(const float* __restrict__ src,
                                                    __nv_bfloat16* __restrict__ hi,
                                                    __nv_bfloat16* __restrict__ lo,
                                                    int n8) {
    int i = blockIdx.x * 256 + threadIdx.x;
    int stride = gridDim.x * 256;
    for (; i < n8; i += stride) {
        const float4* s = (const float4*)src + 2 * (size_t)i;
        float4 x0 = s[0], x1 = s[1];
        float xs[8] = {x0.x, x0.y, x0.z, x0.w, x1.x, x1.y, x1.z, x1.w};
        __nv_bfloat16 h[8], l[8];
#pragma unroll
        for (int k = 0; k < 8; k++) {
            h[k] = __float2bfloat16_rn(xs[k]);
            l[k] = __float2bfloat16_rn(xs[k] - __bfloat162float(h[k]));
        }
        *(uint4*)(hi + 8 * (size_t)i) = *(const uint4*)h;
        *(uint4*)(lo + 8 * (size_t)i) = *(const uint4*)l;
    }
}

// ======================= fused scores GEMM + softmax =======================
// CTA: batch b, 128 v-rows. Active t-tiles only (skip fully-masked).
// 8 warps: warpM=wid&3 (32 rows), warpN=wid>>2 (64 cols). 3xBF16 m16n8k16.
__global__ __launch_bounds__(256, 2) void fused_kernel(const int* __restrict__ lens,
                                                       const float* __restrict__ b_score,
                                                       float* __restrict__ y_utts) {
    extern __shared__ float sm[];
    float* hs = sm + 2 * STAGE_WORDS;                    // 512
    float4* part = (float4*)(hs + 512);                  // 128*2
    float4* run  = part + 128 * 2;                       // 128
    const uint32_t sbase = smem_u32(sm);

    const int tid = threadIdx.x, lane = tid & 31, wid = tid >> 5;
    const int g = lane >> 2, tig = lane & 3;
    const int warpM = wid & 3, warpN = wid >> 2;
    const int b = blockIdx.y, v0 = blockIdx.x * 128;
    const int len_b = lens[b];
    const float bsc = b_score[0];
    const int n_tiles = (len_b + 127) >> 7;              // 2..4

    for (int i = tid; i < T_; i += 256) hs[i] = g_hW[b * T_ + i];
    if (tid < 128) run[tid] = make_float4(-CUDART_INF_F, 0.f, 0.f, 0.f);
    __syncthreads();

    // ---- copy source pointers (per thread) ----
    const int crow = tid >> 1, ch = tid & 1;
    const __nv_bfloat16* pAh = g_Vhi + (size_t)(v0 + crow) * D_ + ch * 8;
    const __nv_bfloat16* pAl = g_Vlo + (size_t)(v0 + crow) * D_ + ch * 8;
    const __nv_bfloat16* pBh = g_Hhi + (size_t)(b * T_ + crow) * D_ + ch * 8;
    const __nv_bfloat16* pBl = g_Hlo + (size_t)(b * T_ + crow) * D_ + ch * 8;
    const uint32_t dst0 = sbase + (crow * STRIDEW + ch * 4) * 4;

#define COPY_CHUNK(ST, TB, K0) do {                                            \
        uint32_t _d = dst0 + (ST) * (STAGE_WORDS * 4);                         \
        size_t _o = (size_t)(TB) * D_ + (K0);                                  \
        CP_ASYNC16(_d,                     pAh + (K0));                        \
        CP_ASYNC16(_d + REG_WORDS * 4,     pAl + (K0));                        \
        CP_ASYNC16(_d + 2 * REG_WORDS * 4, pBh + _o);                          \
        CP_ASYNC16(_d + 3 * REG_WORDS * 4, pBl + _o);                          \
        CP_COMMIT();                                                           \
    } while (0)

    // ---- ldmatrix per-thread word offsets (within a stage) ----
    const int arow = lane & 15;
    const int acol = (lane >> 4) * 4;
    uint32_t aoff[2];
#pragma unroll
    for (int mt = 0; mt < 2; mt++)
        aoff[mt] = sbase + ((warpM * 32 + mt * 16 + arow) * STRIDEW + acol) * 4;
    const int brow = (lane & 7) + ((lane >> 4) & 1) * 8;
    const int bcol = ((lane >> 3) & 1) * 4;
    uint32_t boff[4];
#pragma unroll
    for (int p = 0; p < 4; p++)
        boff[p] = sbase + ((warpN * 64 + p * 16 + brow) * STRIDEW + bcol) * 4;

    int buf = 0;
    COPY_CHUNK(0, 0, 0);

    for (int tt = 0; tt < n_tiles; tt++) {
        const int t0 = tt * 128;

        float acc[2][8][4];
#pragma unroll
        for (int mt = 0; mt < 2; mt++)
#pragma unroll
            for (int nt = 0; nt < 8; nt++)
#pragma unroll
                for (int r = 0; r < 4; r++) acc[mt][nt][r] = 0.f;

        for (int kc = 0; kc < NCHUNK; kc++) {
            CP_WAIT0();
            __syncthreads();
            if (kc + 1 < NCHUNK)      COPY_CHUNK(buf ^ 1, t0, (kc + 1) * KC);
            else if (tt + 1 < n_tiles) COPY_CHUNK(buf ^ 1, t0 + 128, 0);

            const uint32_t so = buf * (STAGE_WORDS * 4);
            uint32_t ah[2][4], al[2][4], bb[4][4];
#pragma unroll
            for (int mt = 0; mt < 2; mt++) {
                LDSM_X4(ah[mt], aoff[mt] + so);
                LDSM_X4(al[mt], aoff[mt] + so + REG_WORDS * 4);
            }
#pragma unroll
            for (int p = 0; p < 4; p++)
                LDSM_X4(bb[p], boff[p] + so + 2 * REG_WORDS * 4);
#pragma unroll
            for (int nt = 0; nt < 8; nt++) {
                const uint32_t b0 = bb[nt >> 1][(nt & 1) * 2];
                const uint32_t b1 = bb[nt >> 1][(nt & 1) * 2 + 1];
#pragma unroll
                for (int mt = 0; mt < 2; mt++) {
                    mma16(acc[mt][nt], ah[mt], b0, b1);   // hi*hi
                    mma16(acc[mt][nt], al[mt], b0, b1);   // lo*hi
                }
            }
#pragma unroll
            for (int p = 0; p < 4; p++)
                LDSM_X4(bb[p], boff[p] + so + 3 * REG_WORDS * 4);
#pragma unroll
            for (int nt = 0; nt < 8; nt++) {
                const uint32_t b0 = bb[nt >> 1][(nt & 1) * 2];
                const uint32_t b1 = bb[nt >> 1][(nt & 1) * 2 + 1];
#pragma unroll
                for (int mt = 0; mt < 2; mt++)
                    mma16(acc[mt][nt], ah[mt], b0, b1);   // hi*lo
            }
            buf ^= 1;
        }

        // ---- epilogue: masked softmax partials per (row, warpN half) ----
#pragma unroll
        for (int mt = 0; mt < 2; mt++)
#pragma unroll
            for (int rh = 0; rh < 2; rh++) {
                float m = -CUDART_INF_F;
#pragma unroll
                for (int nt = 0; nt < 8; nt++)
#pragma unroll
                    for (int j2 = 0; j2 < 2; j2++) {
                        int tc = t0 + warpN * 64 + nt * 8 + 2 * tig + j2;
                        float x = acc[mt][nt][rh * 2 + j2];
                        m = fmaxf(m, tc < len_b ? x : -CUDART_INF_F);
                    }
                m = fmaxf(m, __shfl_xor_sync(0xffffffffu, m, 1));
                m = fmaxf(m, __shfl_xor_sync(0xffffffffu, m, 2));
                float l = 0.f, w = 0.f;
#pragma unroll
                for (int nt = 0; nt < 8; nt++)
#pragma unroll
                    for (int j2 = 0; j2 < 2; j2++) {
                        int tc = t0 + warpN * 64 + nt * 8 + 2 * tig + j2;
                        if (tc < len_b) {
                            float e = __expf(acc[mt][nt][rh * 2 + j2] - m);
                            l += e;
                            w += e * hs[tc];
                        }
                    }
                l += __shfl_xor_sync(0xffffffffu, l, 1);
                l += __shfl_xor_sync(0xffffffffu, l, 2);
                w += __shfl_xor_sync(0xffffffffu, w, 1);
                w += __shfl_xor_sync(0xffffffffu, w, 2);
                if (tig == 0) {
                    int row = warpM * 32 + mt * 16 + g + rh * 8;
                    part[row * 2 + warpN] = make_float4(m, l, w, 0.f);
                }
            }
        __syncthreads();
        if (tid < 128) {
            float4 r = run[tid];
            float4 p0 = part[tid * 2 + 0];
            float4 p1 = part[tid * 2 + 1];
            float nm = fmaxf(r.x, fmaxf(p0.x, p1.x));
            float er = __expf(r.x - nm);
            float e0 = __expf(p0.x - nm);
            float e1 = __expf(p1.x - nm);
            r.y = r.y * er + p0.y * e0 + p1.y * e1;
            r.z = r.z * er + p0.z * e0 + p1.z * e1;
            r.x = nm;
            run[tid] = r;
        }
        __syncthreads();   // part/run settled before next tile's epilogue
    }

    if (tid < 128)
        y_utts[b * V_ + v0 + tid] = run[tid].z / run[tid].y + bsc;
#undef COPY_CHUNK
}

// ======================= acts path =========================================
__global__ __launch_bounds__(128) void acts_kernel(const float* __restrict__ C_acts,
                                                   const float* __restrict__ c_utt) {
    __shared__ float cu[D_];
    __shared__ float p[A_];
    __shared__ float w4[4], w4b[4];
    const int b = blockIdx.x;
    const int tid = threadIdx.x;
    const int warp = tid >> 5, lane = tid & 31;

    for (int d = tid; d < D_; d += 128) cu[d] = c_utt[b * D_ + d];
    __syncthreads();

    const float* Cb = C_acts + (size_t)b * A_ * D_;
    const float* row = Cb + (size_t)tid * D_;
    float s = 0.f;
    for (int d = 0; d < D_; d += 4) {
        float4 r = *(const float4*)(row + d);
        s += r.x * cu[d] + r.y * cu[d + 1] + r.z * cu[d + 2] + r.w * cu[d + 3];
    }
    float m = s;
#pragma unroll
    for (int o = 16; o; o >>= 1) m = fmaxf(m, __shfl_xor_sync(0xffffffffu, m, o));
    if (lane == 0) w4[warp] = m;
    __syncthreads();
    m = fmaxf(fmaxf(w4[0], w4[1]), fmaxf(w4[2], w4[3]));

    float e = __expf(s - m);
    float smv = e;
#pragma unroll
    for (int o = 16; o; o >>= 1) smv += __shfl_xor_sync(0xffffffffu, smv, o);
    if (lane == 0) w4b[warp] = smv;
    __syncthreads();
    float tot = w4b[0] + w4b[1] + w4b[2] + w4b[3];
    p[tid] = e / tot;
    __syncthreads();

    for (int d = tid; d < D_; d += 128) {
        float q = 0.f;
        for (int a = 0; a < A_; a++) q = fmaf(p[a], Cb[(size_t)a * D_ + d], q);
        g_q[b * D_ + d] = q;
    }
}

// ======================= y_acts = q @ vals^T ===============================
#define BB_ 4
__global__ __launch_bounds__(128) void yacts_kernel(const float* __restrict__ vals,
                                                    float* __restrict__ y_acts) {
    __shared__ float qs[BB_][D_];
    const int v = blockIdx.x * 128 + threadIdx.x;
    const int b0 = blockIdx.y * BB_;
    for (int f = threadIdx.x; f < BB_ * D_; f += 128)
        ((float*)qs)[f] = g_q[b0 * D_ + f];
    __syncthreads();

    float acc[BB_];
#pragma unroll
    for (int bb = 0; bb < BB_; bb++) acc[bb] = 0.f;

    const float* vrow = vals + (size_t)v * D_;
    for (int d = 0; d < D_; d += 4) {
        float4 r = *(const float4*)(vrow + d);
#pragma unroll
        for (int bb = 0; bb < BB_; bb++) {
            acc[bb] = fmaf(r.x, qs[bb][d], acc[bb]);
            acc[bb] = fmaf(r.y, qs[bb][d + 1], acc[bb]);
            acc[bb] = fmaf(r.z, qs[bb][d + 2], acc[bb]);
            acc[bb] = fmaf(r.w, qs[bb][d + 3], acc[bb]);
        }
    }
#pragma unroll
    for (int bb = 0; bb < BB_; bb++)
        y_acts[(size_t)(b0 + bb) * V_ + v] = acc[bb];
}

// ===========================================================================
extern "C" void kernel_launch(void* const* d_in, const int* in_sizes, int n_in,
                              void* d_out, int out_size) {
    const float* H       = (const float*)d_in[0];
    const float* c_utt   = (const float*)d_in[1];
    const float* C_acts  = (const float*)d_in[2];
    const float* C_vals  = (const float*)d_in[3];
    const float* W       = (const float*)d_in[4];
    const float* b_score = (const float*)d_in[5];
    const int*   lens    = (const int*)d_in[6];

    float* y_utts = (float*)d_out;
    float* y_acts = (float*)d_out + (size_t)B_ * V_;

    static __nv_bfloat16* p_Vhi = nullptr;
    static __nv_bfloat16* p_Vlo = nullptr;
    if (!p_Vhi) {
        cudaGetSymbolAddress((void**)&p_Vhi, g_Vhi);
        cudaGetSymbolAddress((void**)&p_Vlo, g_Vlo);
        cudaFuncSetAttribute(fused_kernel,
                             cudaFuncAttributeMaxDynamicSharedMemorySize, SMEM_BYTES);
    }

    prep_h_kernel<<<(B_ * T_) / 4, 256>>>(H, W);
    split_kernel<<<128, 256>>>(C_vals, p_Vhi, p_Vlo, V_ * D_ / 8);
    fused_kernel<<<dim3(V_ / 128, B_), 256, SMEM_BYTES>>>(lens, b_score, y_utts);
    acts_kernel<<<B_, 128>>>(C_acts, c_utt);
    yacts_kernel<<<dim3(V_ / 128, B_ / BB_), 128>>>(C_vals, y_acts);
}

// round 7
// speedup vs baseline: 2.5811x; 1.0224x over previous
#include <cuda_runtime.h>
#include <cuda_bf16.h>
#include <math_constants.h>
#include <stdint.h>

#define B_ 128
#define T_ 512
#define D_ 400
#define V_ 1024
#define A_ 128

#define KC      16
#define NCHUNK  25              // 25*16 = 400
#define STRIDEW 12              // words per row (8 data + 4 pad), conflict-free
#define REG_WORDS   (128 * STRIDEW)
#define STAGE_WORDS (4 * REG_WORDS)     // Ahi, Alo, Bhi, Blo
#define STAGE_BYTES (STAGE_WORDS * 4)   // 24576
#define NSTAGE 4
#define SMEM_WORDS  (NSTAGE * STAGE_WORDS + 512 + 1024 + 512)
#define SMEM_BYTES  (SMEM_WORDS * 4)    // 106496

// -------- scratch (device globals; no runtime allocation allowed) ----------
__device__ __align__(256) __nv_bfloat16 g_Hhi[B_ * T_ * D_];
__device__ __align__(256) __nv_bfloat16 g_Hlo[B_ * T_ * D_];
__device__ __align__(256) __nv_bfloat16 g_Vhi[V_ * D_];
__device__ __align__(256) __nv_bfloat16 g_Vlo[V_ * D_];
__device__ float g_hW[B_ * T_];
__device__ float g_p[B_ * A_];
__device__ float g_q[B_ * D_];

// ======================= helpers ===========================================
__device__ __forceinline__ uint32_t smem_u32(const void* p) {
    uint32_t a;
    asm("{ .reg .u64 t; cvta.to.shared.u64 t, %1; cvt.u32.u64 %0, t; }"
        : "=r"(a) : "l"(p));
    return a;
}
#define CP_ASYNC16(dst, src) \
    asm volatile("cp.async.cg.shared.global [%0], [%1], 16;" \
                 :: "r"(dst), "l"(src) : "memory")
#define CP_COMMIT() asm volatile("cp.async.commit_group;" ::: "memory")
#define CP_WAIT2()  asm volatile("cp.async.wait_group 2;" ::: "memory")

#define LDSM_X4(R, addr)                                                      \
    asm volatile("ldmatrix.sync.aligned.m8n8.x4.shared.b16 {%0,%1,%2,%3}, [%4];" \
        : "=r"((R)[0]), "=r"((R)[1]), "=r"((R)[2]), "=r"((R)[3]) : "r"(addr))

__device__ __forceinline__ void mma16(float d[4], const uint32_t a[4],
                                      const uint32_t b0, const uint32_t b1) {
    asm volatile(
        "mma.sync.aligned.m16n8k16.row.col.f32.bf16.bf16.f32 "
        "{%0,%1,%2,%3}, {%4,%5,%6,%7}, {%8,%9}, {%0,%1,%2,%3};"
        : "+f"(d[0]), "+f"(d[1]), "+f"(d[2]), "+f"(d[3])
        : "r"(a[0]), "r"(a[1]), "r"(a[2]), "r"(a[3]), "r"(b0), "r"(b1));
}

// ============ prep: H -> bf16 hi/lo split AND hW = H.W (warp per row) ======
__global__ __launch_bounds__(256) void prep_h_kernel(const float* __restrict__ H,
                                                     const float* __restrict__ W,
                                                     const int* __restrict__ lens) {
    __shared__ float sW[D_];
    for (int d = threadIdx.x; d < D_; d += 256) sW[d] = W[d];
    __syncthreads();

    const int wid = threadIdx.x >> 5, lane = threadIdx.x & 31;
    const size_t row = (size_t)blockIdx.x * 8 + wid;
    const int t = (int)(row & (T_ - 1));
    const int b = (int)(row >> 9);
    if (t >= lens[b]) return;                 // whole warp exits together

    const float* src = H + row * D_;
    float s = 0.f;
    for (int d4 = lane; d4 < D_ / 4; d4 += 32) {
        float4 x = ((const float4*)src)[d4];
        __nv_bfloat16 h[4], l[4];
        h[0] = __float2bfloat16_rn(x.x); l[0] = __float2bfloat16_rn(x.x - __bfloat162float(h[0]));
        h[1] = __float2bfloat16_rn(x.y); l[1] = __float2bfloat16_rn(x.y - __bfloat162float(h[1]));
        h[2] = __float2bfloat16_rn(x.z); l[2] = __float2bfloat16_rn(x.z - __bfloat162float(h[2]));
        h[3] = __float2bfloat16_rn(x.w); l[3] = __float2bfloat16_rn(x.w - __bfloat162float(h[3]));
        *(uint2*)(g_Hhi + row * D_ + d4 * 4) = *(const uint2*)h;
        *(uint2*)(g_Hlo + row * D_ + d4 * 4) = *(const uint2*)l;
        const float* w = sW + d4 * 4;
        s += x.x * w[0] + x.y * w[1] + x.z * w[2] + x.w * w[3];
    }
#pragma unroll
    for (int o = 16; o; o >>= 1) s += __shfl_xor_sync(0xffffffffu, s, o);
    if (lane == 0) g_hW[row] = s;
}

// ======================= V: bf16 hi/lo split ===============================
__global__ __launch_bounds__(256) void split_kernel(const float* __restrict__ src,
                                                    __nv_bfloat16* __restrict__ hi,
                                                    __nv_bfloat16* __restrict__ lo,
                                                    int n8) {
    int i = blockIdx.x * 256 + threadIdx.x;
    int stride = gridDim.x * 256;
    for (; i < n8; i += stride) {
        const float4* s = (const float4*)src + 2 * (size_t)i;
        float4 x0 = s[0], x1 = s[1];
        float xs[8] = {x0.x, x0.y, x0.z, x0.w, x1.x, x1.y, x1.z, x1.w};
        __nv_bfloat16 h[8], l[8];
#pragma unroll
        for (int k = 0; k < 8; k++) {
            h[k] = __float2bfloat16_rn(xs[k]);
            l[k] = __float2bfloat16_rn(xs[k] - __bfloat162float(h[k]));
        }
        *(uint4*)(hi + 8 * (size_t)i) = *(const uint4*)h;
        *(uint4*)(lo + 8 * (size_t)i) = *(const uint4*)l;
    }
}

// ======================= fused scores GEMM + softmax =======================
__global__ __launch_bounds__(256, 2) void fused_kernel(const int* __restrict__ lens,
                                                       const float* __restrict__ b_score,
                                                       float* __restrict__ y_utts) {
    extern __shared__ float sm[];
    float* hs = sm + NSTAGE * STAGE_WORDS;               // 512
    float4* part = (float4*)(hs + 512);                  // 256 float4
    float4* run  = part + 256;                           // 128 float4
    const uint32_t sbase = smem_u32(sm);

    const int tid = threadIdx.x, lane = tid & 31, wid = tid >> 5;
    const int g = lane >> 2, tig = lane & 3;
    const int warpM = wid & 3, warpN = wid >> 2;
    const int b = blockIdx.y, v0 = blockIdx.x * 128;
    const int len_b = lens[b];
    const float bsc = b_score[0];
    const int n_tiles = (len_b + 127) >> 7;
    const int total_c = n_tiles * NCHUNK;

    for (int i = tid; i < T_; i += 256) hs[i] = g_hW[b * T_ + i];
    if (tid < 128) run[tid] = make_float4(-CUDART_INF_F, 0.f, 0.f, 0.f);
    __syncthreads();

    // ---- per-thread copy sources ----
    const int crow = tid >> 1, ch = tid & 1;
    const __nv_bfloat16* pAh = g_Vhi + (size_t)(v0 + crow) * D_ + ch * 8;
    const __nv_bfloat16* pAl = g_Vlo + (size_t)(v0 + crow) * D_ + ch * 8;
    const __nv_bfloat16* pBh = g_Hhi + (size_t)(b * T_ + crow) * D_ + ch * 8;
    const __nv_bfloat16* pBl = g_Hlo + (size_t)(b * T_ + crow) * D_ + ch * 8;
    const uint32_t dst0 = sbase + (crow * STRIDEW + ch * 4) * 4;

    int cp_t = 0, cp_k = 0;                   // next chunk to copy
#define COPY_NEXT(ST) do {                                                     \
        uint32_t _d = dst0 + (ST) * STAGE_BYTES;                               \
        size_t _o = (size_t)cp_t * D_ + cp_k;                                  \
        CP_ASYNC16(_d,                     pAh + cp_k);                        \
        CP_ASYNC16(_d + REG_WORDS * 4,     pAl + cp_k);                        \
        CP_ASYNC16(_d + 2 * REG_WORDS * 4, pBh + _o);                          \
        CP_ASYNC16(_d + 3 * REG_WORDS * 4, pBl + _o);                          \
        cp_k += KC; if (cp_k == D_) { cp_k = 0; cp_t += 128; }                 \
    } while (0)

    // ---- ldmatrix per-thread offsets ----
    const int arow = lane & 15;
    const int acol = (lane >> 4) * 4;
    uint32_t aoff[2];
#pragma unroll
    for (int mt = 0; mt < 2; mt++)
        aoff[mt] = sbase + ((warpM * 32 + mt * 16 + arow) * STRIDEW + acol) * 4;
    const int brow = (lane & 7) + ((lane >> 4) & 1) * 8;
    const int bcol = ((lane >> 3) & 1) * 4;
    uint32_t boff[4];
#pragma unroll
    for (int p = 0; p < 4; p++)
        boff[p] = sbase + ((warpN * 64 + p * 16 + brow) * STRIDEW + bcol) * 4;

    // ---- prologue: 3 chunks in flight ----
    COPY_NEXT(0); CP_COMMIT();
    COPY_NEXT(1); CP_COMMIT();
    COPY_NEXT(2); CP_COMMIT();

    int fc = 0;
    for (int tt = 0; tt < n_tiles; tt++) {
        const int t0 = tt * 128;

        float acc[2][8][4];
#pragma unroll
        for (int mt = 0; mt < 2; mt++)
#pragma unroll
            for (int nt = 0; nt < 8; nt++)
#pragma unroll
                for (int r = 0; r < 4; r++) acc[mt][nt][r] = 0.f;

        for (int kc = 0; kc < NCHUNK; kc++, fc++) {
            CP_WAIT2();                       // chunk fc landed (this thread)
            __syncthreads();                  // all threads' chunk fc visible
            if (fc + 3 < total_c) COPY_NEXT((fc + 3) & 3);
            CP_COMMIT();                      // always commit (group == chunk)

            const uint32_t so = (fc & 3) * STAGE_BYTES;
            uint32_t ah[2][4], al[2][4], bb[4][4];
#pragma unroll
            for (int mt = 0; mt < 2; mt++) {
                LDSM_X4(ah[mt], aoff[mt] + so);
                LDSM_X4(al[mt], aoff[mt] + so + REG_WORDS * 4);
            }
#pragma unroll
            for (int p = 0; p < 4; p++)
                LDSM_X4(bb[p], boff[p] + so + 2 * REG_WORDS * 4);
#pragma unroll
            for (int nt = 0; nt < 8; nt++) {
                const uint32_t b0 = bb[nt >> 1][(nt & 1) * 2];
                const uint32_t b1 = bb[nt >> 1][(nt & 1) * 2 + 1];
#pragma unroll
                for (int mt = 0; mt < 2; mt++) {
                    mma16(acc[mt][nt], ah[mt], b0, b1);   // hi*hi
                    mma16(acc[mt][nt], al[mt], b0, b1);   // lo*hi
                }
            }
#pragma unroll
            for (int p = 0; p < 4; p++)
                LDSM_X4(bb[p], boff[p] + so + 3 * REG_WORDS * 4);
#pragma unroll
            for (int nt = 0; nt < 8; nt++) {
                const uint32_t b0 = bb[nt >> 1][(nt & 1) * 2];
                const uint32_t b1 = bb[nt >> 1][(nt & 1) * 2 + 1];
#pragma unroll
                for (int mt = 0; mt < 2; mt++)
                    mma16(acc[mt][nt], ah[mt], b0, b1);   // hi*lo
            }
        }

        // ---- epilogue: masked softmax partials ----
#pragma unroll
        for (int mt = 0; mt < 2; mt++)
#pragma unroll
            for (int rh = 0; rh < 2; rh++) {
                float m = -CUDART_INF_F;
#pragma unroll
                for (int nt = 0; nt < 8; nt++)
#pragma unroll
                    for (int j2 = 0; j2 < 2; j2++) {
                        int tc = t0 + warpN * 64 + nt * 8 + 2 * tig + j2;
                        float x = acc[mt][nt][rh * 2 + j2];
                        m = fmaxf(m, tc < len_b ? x : -CUDART_INF_F);
                    }
                m = fmaxf(m, __shfl_xor_sync(0xffffffffu, m, 1));
                m = fmaxf(m, __shfl_xor_sync(0xffffffffu, m, 2));
                float l = 0.f, w = 0.f;
#pragma unroll
                for (int nt = 0; nt < 8; nt++)
#pragma unroll
                    for (int j2 = 0; j2 < 2; j2++) {
                        int tc = t0 + warpN * 64 + nt * 8 + 2 * tig + j2;
                        if (tc < len_b) {
                            float e = __expf(acc[mt][nt][rh * 2 + j2] - m);
                            l += e;
                            w += e * hs[tc];
                        }
                    }
                l += __shfl_xor_sync(0xffffffffu, l, 1);
                l += __shfl_xor_sync(0xffffffffu, l, 2);
                w += __shfl_xor_sync(0xffffffffu, w, 1);
                w += __shfl_xor_sync(0xffffffffu, w, 2);
                if (tig == 0) {
                    int row = warpM * 32 + mt * 16 + g + rh * 8;
                    part[row * 2 + warpN] = make_float4(m, l, w, 0.f);
                }
            }
        __syncthreads();
        if (tid < 128) {
            float4 r = run[tid];
            float4 p0 = part[tid * 2 + 0];
            float4 p1 = part[tid * 2 + 1];
            float nm = fmaxf(r.x, fmaxf(p0.x, p1.x));
            float er = __expf(r.x - nm);
            float e0 = __expf(p0.x - nm);
            float e1 = __expf(p1.x - nm);
            r.y = r.y * er + p0.y * e0 + p1.y * e1;
            r.z = r.z * er + p0.z * e0 + p1.z * e1;
            r.x = nm;
            run[tid] = r;
        }
        __syncthreads();
    }

    if (tid < 128)
        y_utts[b * V_ + v0 + tid] = run[tid].z / run[tid].y + bsc;
#undef COPY_NEXT
}

// ======================= acts phase A: softmax probs =======================
__global__ __launch_bounds__(128) void acts_score_kernel(const float* __restrict__ C_acts,
                                                         const float* __restrict__ c_utt) {
    __shared__ float cu[D_];
    __shared__ float w4[4], w4b[4];
    const int b = blockIdx.x;
    const int tid = threadIdx.x;
    const int warp = tid >> 5, lane = tid & 31;

    for (int d = tid; d < D_; d += 128) cu[d] = c_utt[b * D_ + d];
    __syncthreads();

    const float* row = C_acts + ((size_t)b * A_ + tid) * D_;
    float s = 0.f;
    for (int d = 0; d < D_; d += 4) {
        float4 r = *(const float4*)(row + d);
        s += r.x * cu[d] + r.y * cu[d + 1] + r.z * cu[d + 2] + r.w * cu[d + 3];
    }
    float m = s;
#pragma unroll
    for (int o = 16; o; o >>= 1) m = fmaxf(m, __shfl_xor_sync(0xffffffffu, m, o));
    if (lane == 0) w4[warp] = m;
    __syncthreads();
    m = fmaxf(fmaxf(w4[0], w4[1]), fmaxf(w4[2], w4[3]));

    float e = __expf(s - m);
    float smv = e;
#pragma unroll
    for (int o = 16; o; o >>= 1) smv += __shfl_xor_sync(0xffffffffu, smv, o);
    if (lane == 0) w4b[warp] = smv;
    __syncthreads();
    float tot = w4b[0] + w4b[1] + w4b[2] + w4b[3];
    g_p[b * A_ + tid] = e / tot;
}

// ======================= acts phase B: q = p @ C_acts ======================
__global__ __launch_bounds__(128) void acts_q_kernel(const float* __restrict__ C_acts) {
    __shared__ float p[A_];
    const int b = blockIdx.y;
    const int d = blockIdx.x * 100 + threadIdx.x;
    if (threadIdx.x < A_) p[threadIdx.x] = g_p[b * A_ + threadIdx.x];
    __syncthreads();
    if (threadIdx.x >= 100) return;
    const float* Cb = C_acts + (size_t)b * A_ * D_ + d;
    float q = 0.f;
#pragma unroll 4
    for (int a = 0; a < A_; a++) q = fmaf(p[a], Cb[(size_t)a * D_], q);
    g_q[b * D_ + d] = q;
}

// ======================= y_acts: warp per v-row ============================
__global__ __launch_bounds__(256) void yacts_kernel(const float* __restrict__ vals,
                                                    float* __restrict__ y_acts) {
    __shared__ float qs[16 * D_];
    const int tid = threadIdx.x, lane = tid & 31, wid = tid >> 5;
    const int b0 = blockIdx.y * 16;
    const int v = blockIdx.x * 8 + wid;

    for (int f = tid; f < 16 * D_; f += 256) qs[f] = g_q[b0 * D_ + f];
    __syncthreads();

    float acc[16];
#pragma unroll
    for (int bb = 0; bb < 16; bb++) acc[bb] = 0.f;

    const float4* vr = (const float4*)(vals + (size_t)v * D_);
    const float4* q4 = (const float4*)qs;
    for (int d4 = lane; d4 < D_ / 4; d4 += 32) {
        float4 r = vr[d4];
#pragma unroll
        for (int bb = 0; bb < 16; bb++) {
            float4 q = q4[bb * (D_ / 4) + d4];
            acc[bb] += r.x * q.x + r.y * q.y + r.z * q.z + r.w * q.w;
        }
    }
#pragma unroll
    for (int o = 16; o; o >>= 1)
#pragma unroll
        for (int bb = 0; bb < 16; bb++)
            acc[bb] += __shfl_xor_sync(0xffffffffu, acc[bb], o);
    if (lane == 0) {
#pragma unroll
        for (int bb = 0; bb < 16; bb++)
            y_acts[(size_t)(b0 + bb) * V_ + v] = acc[bb];
    }
}

// ===========================================================================
extern "C" void kernel_launch(void* const* d_in, const int* in_sizes, int n_in,
                              void* d_out, int out_size) {
    const float* H       = (const float*)d_in[0];
    const float* c_utt   = (const float*)d_in[1];
    const float* C_acts  = (const float*)d_in[2];
    const float* C_vals  = (const float*)d_in[3];
    const float* W       = (const float*)d_in[4];
    const float* b_score = (const float*)d_in[5];
    const int*   lens    = (const int*)d_in[6];

    float* y_utts = (float*)d_out;
    float* y_acts = (float*)d_out + (size_t)B_ * V_;

    static __nv_bfloat16* p_Vhi = nullptr;
    static __nv_bfloat16* p_Vlo = nullptr;
    if (!p_Vhi) {
        cudaGetSymbolAddress((void**)&p_Vhi, g_Vhi);
        cudaGetSymbolAddress((void**)&p_Vlo, g_Vlo);
        cudaFuncSetAttribute(fused_kernel,
                             cudaFuncAttributeMaxDynamicSharedMemorySize, SMEM_BYTES);
    }

    prep_h_kernel<<<(B_ * T_) / 8, 256>>>(H, W, lens);
    split_kernel<<<128, 256>>>(C_vals, p_Vhi, p_Vlo, V_ * D_ / 8);
    fused_kernel<<<dim3(V_ / 128, B_), 256, SMEM_BYTES>>>(lens, b_score, y_utts);
    acts_score_kernel<<<B_, 128>>>(C_acts, c_utt);
    acts_q_kernel<<<dim3(4, B_), 128>>>(C_acts);
    yacts_kernel<<<dim3(V_ / 8, B_ / 16), 256>>>(C_vals, y_acts);
}

// round 8
// speedup vs baseline: 2.5998x; 1.0072x over previous
#include <cuda_runtime.h>
#include <cuda_bf16.h>
#include <math_constants.h>
#include <stdint.h>

#define B_ 128
#define T_ 512
#define D_ 400
#define DP_ 416                 // padded K (pad is zero-initialized, never written)
#define V_ 1024
#define A_ 128

#define KC      32              // K elems per chunk (two m16n8k16 steps)
#define NCHUNK  13              // 13*32 = 416
#define STRIDEW 20              // words per row (16 data + 4 pad), conflict-free
#define REG_WORDS   (128 * STRIDEW)
#define STAGE_WORDS (4 * REG_WORDS)     // Ahi, Alo, Bhi, Blo
#define STAGE_BYTES (STAGE_WORDS * 4)   // 40960
#define NSTAGE 2
#define SMEM_WORDS  (NSTAGE * STAGE_WORDS + 512 + 1024 + 512)
#define SMEM_BYTES  (SMEM_WORDS * 4)    // 90112

// -------- scratch (device globals; zero-initialized at load) ---------------
__device__ __align__(256) __nv_bfloat16 g_Hhi[B_ * T_ * DP_];
__device__ __align__(256) __nv_bfloat16 g_Hlo[B_ * T_ * DP_];
__device__ __align__(256) __nv_bfloat16 g_Vhi[V_ * DP_];
__device__ __align__(256) __nv_bfloat16 g_Vlo[V_ * DP_];
__device__ float g_hW[B_ * T_];
__device__ float g_p[B_ * A_];
__device__ float g_q[B_ * D_];

// ======================= helpers ===========================================
__device__ __forceinline__ uint32_t smem_u32(const void* p) {
    uint32_t a;
    asm("{ .reg .u64 t; cvta.to.shared.u64 t, %1; cvt.u32.u64 %0, t; }"
        : "=r"(a) : "l"(p));
    return a;
}
#define CP_ASYNC16(dst, src) \
    asm volatile("cp.async.cg.shared.global [%0], [%1], 16;" \
                 :: "r"(dst), "l"(src) : "memory")
#define CP_COMMIT() asm volatile("cp.async.commit_group;" ::: "memory")
#define CP_WAIT0()  asm volatile("cp.async.wait_group 0;" ::: "memory")

#define LDSM_X4(R, addr)                                                      \
    asm volatile("ldmatrix.sync.aligned.m8n8.x4.shared.b16 {%0,%1,%2,%3}, [%4];" \
        : "=r"((R)[0]), "=r"((R)[1]), "=r"((R)[2]), "=r"((R)[3]) : "r"(addr))

__device__ __forceinline__ void mma16(float d[4], const uint32_t a[4],
                                      const uint32_t b0, const uint32_t b1) {
    asm volatile(
        "mma.sync.aligned.m16n8k16.row.col.f32.bf16.bf16.f32 "
        "{%0,%1,%2,%3}, {%4,%5,%6,%7}, {%8,%9}, {%0,%1,%2,%3};"
        : "+f"(d[0]), "+f"(d[1]), "+f"(d[2]), "+f"(d[3])
        : "r"(a[0]), "r"(a[1]), "r"(a[2]), "r"(a[3]), "r"(b0), "r"(b1));
}

// ============ prep: H -> bf16 hi/lo split AND hW = H.W (warp per row) ======
__global__ __launch_bounds__(256) void prep_h_kernel(const float* __restrict__ H,
                                                     const float* __restrict__ W,
                                                     const int* __restrict__ lens) {
    __shared__ float sW[D_];
    for (int d = threadIdx.x; d < D_; d += 256) sW[d] = W[d];
    __syncthreads();

    const int wid = threadIdx.x >> 5, lane = threadIdx.x & 31;
    const size_t row = (size_t)blockIdx.x * 8 + wid;
    const int t = (int)(row & (T_ - 1));
    const int b = (int)(row >> 9);
    if (t >= lens[b]) return;                 // whole warp exits together

    const float* src = H + row * D_;
    float s = 0.f;
    for (int d4 = lane; d4 < D_ / 4; d4 += 32) {
        float4 x = ((const float4*)src)[d4];
        __nv_bfloat16 h[4], l[4];
        h[0] = __float2bfloat16_rn(x.x); l[0] = __float2bfloat16_rn(x.x - __bfloat162float(h[0]));
        h[1] = __float2bfloat16_rn(x.y); l[1] = __float2bfloat16_rn(x.y - __bfloat162float(h[1]));
        h[2] = __float2bfloat16_rn(x.z); l[2] = __float2bfloat16_rn(x.z - __bfloat162float(h[2]));
        h[3] = __float2bfloat16_rn(x.w); l[3] = __float2bfloat16_rn(x.w - __bfloat162float(h[3]));
        *(uint2*)(g_Hhi + row * DP_ + d4 * 4) = *(const uint2*)h;
        *(uint2*)(g_Hlo + row * DP_ + d4 * 4) = *(const uint2*)l;
        const float* w = sW + d4 * 4;
        s += x.x * w[0] + x.y * w[1] + x.z * w[2] + x.w * w[3];
    }
#pragma unroll
    for (int o = 16; o; o >>= 1) s += __shfl_xor_sync(0xffffffffu, s, o);
    if (lane == 0) g_hW[row] = s;
}

// ======================= V: bf16 hi/lo split (warp per row) ================
__global__ __launch_bounds__(256) void split_v_kernel(const float* __restrict__ src) {
    const int wid = threadIdx.x >> 5, lane = threadIdx.x & 31;
    const size_t v = (size_t)blockIdx.x * 8 + wid;
    const float* s = src + v * D_;
    for (int d4 = lane; d4 < D_ / 4; d4 += 32) {
        float4 x = ((const float4*)s)[d4];
        __nv_bfloat16 h[4], l[4];
        h[0] = __float2bfloat16_rn(x.x); l[0] = __float2bfloat16_rn(x.x - __bfloat162float(h[0]));
        h[1] = __float2bfloat16_rn(x.y); l[1] = __float2bfloat16_rn(x.y - __bfloat162float(h[1]));
        h[2] = __float2bfloat16_rn(x.z); l[2] = __float2bfloat16_rn(x.z - __bfloat162float(h[2]));
        h[3] = __float2bfloat16_rn(x.w); l[3] = __float2bfloat16_rn(x.w - __bfloat162float(h[3]));
        *(uint2*)(g_Vhi + v * DP_ + d4 * 4) = *(const uint2*)h;
        *(uint2*)(g_Vlo + v * DP_ + d4 * 4) = *(const uint2*)l;
    }
}

// ======================= fused scores GEMM + softmax =======================
__global__ __launch_bounds__(256, 2) void fused_kernel(const int* __restrict__ lens,
                                                       const float* __restrict__ b_score,
                                                       float* __restrict__ y_utts) {
    extern __shared__ float sm[];
    float* hs = sm + NSTAGE * STAGE_WORDS;               // 512
    float4* part = (float4*)(hs + 512);                  // 256 float4
    float4* run  = part + 256;                           // 128 float4
    const uint32_t sbase = smem_u32(sm);

    const int tid = threadIdx.x, lane = tid & 31, wid = tid >> 5;
    const int g = lane >> 2, tig = lane & 3;
    const int warpM = wid & 3, warpN = wid >> 2;
    const int b = blockIdx.y, v0 = blockIdx.x * 128;
    const int len_b = lens[b];
    const float bsc = b_score[0];
    const int n_tiles = (len_b + 127) >> 7;
    const int total_c = n_tiles * NCHUNK;

    for (int i = tid; i < T_; i += 256) hs[i] = g_hW[b * T_ + i];
    if (tid < 128) run[tid] = make_float4(-CUDART_INF_F, 0.f, 0.f, 0.f);
    __syncthreads();

    // ---- per-thread copy sources: 2 threads/row, each covers 16 elems ----
    const int crow = tid >> 1, ch = tid & 1;
    const __nv_bfloat16* pAh = g_Vhi + (size_t)(v0 + crow) * DP_ + ch * 16;
    const __nv_bfloat16* pAl = g_Vlo + (size_t)(v0 + crow) * DP_ + ch * 16;
    const __nv_bfloat16* pBh = g_Hhi + (size_t)(b * T_ + crow) * DP_ + ch * 16;
    const __nv_bfloat16* pBl = g_Hlo + (size_t)(b * T_ + crow) * DP_ + ch * 16;
    const uint32_t dst0 = sbase + (crow * STRIDEW + ch * 8) * 4;

    int cp_t = 0, cp_k = 0;
#define COPY_NEXT(ST) do {                                                     \
        uint32_t _d = dst0 + (ST) * STAGE_BYTES;                               \
        size_t _o = (size_t)cp_t * DP_ + cp_k;                                 \
        CP_ASYNC16(_d,                          pAh + cp_k);                   \
        CP_ASYNC16(_d + 16,                     pAh + cp_k + 8);               \
        CP_ASYNC16(_d + REG_WORDS * 4,          pAl + cp_k);                   \
        CP_ASYNC16(_d + REG_WORDS * 4 + 16,     pAl + cp_k + 8);               \
        CP_ASYNC16(_d + 2 * REG_WORDS * 4,      pBh + _o);                     \
        CP_ASYNC16(_d + 2 * REG_WORDS * 4 + 16, pBh + _o + 8);                 \
        CP_ASYNC16(_d + 3 * REG_WORDS * 4,      pBl + _o);                     \
        CP_ASYNC16(_d + 3 * REG_WORDS * 4 + 16, pBl + _o + 8);                 \
        cp_k += KC; if (cp_k == DP_) { cp_k = 0; cp_t += 128; }                \
    } while (0)

    // ---- ldmatrix per-thread offsets ----
    const int arow = lane & 15;
    const int acol = (lane >> 4) * 4;
    uint32_t aoff[2];
#pragma unroll
    for (int mt = 0; mt < 2; mt++)
        aoff[mt] = sbase + ((warpM * 32 + mt * 16 + arow) * STRIDEW + acol) * 4;
    const int brow = (lane & 7) + ((lane >> 4) & 1) * 8;
    const int bcol = ((lane >> 3) & 1) * 4;
    uint32_t boff[4];
#pragma unroll
    for (int p = 0; p < 4; p++)
        boff[p] = sbase + ((warpN * 64 + p * 16 + brow) * STRIDEW + bcol) * 4;

    COPY_NEXT(0); CP_COMMIT();

    int fc = 0;
    for (int tt = 0; tt < n_tiles; tt++) {
        const int t0 = tt * 128;

        float acc[2][8][4];
#pragma unroll
        for (int mt = 0; mt < 2; mt++)
#pragma unroll
            for (int nt = 0; nt < 8; nt++)
#pragma unroll
                for (int r = 0; r < 4; r++) acc[mt][nt][r] = 0.f;

        for (int kc = 0; kc < NCHUNK; kc++, fc++) {
            CP_WAIT0();                       // chunk fc landed (this thread)
            __syncthreads();                  // published to all; prev stage free
            if (fc + 1 < total_c) COPY_NEXT((fc + 1) & 1);
            CP_COMMIT();

            const uint32_t so = (fc & 1) * STAGE_BYTES;
#pragma unroll
            for (int s = 0; s < 2; s++) {
                const uint32_t so2 = so + s * 32;     // +8 words per k-step
                uint32_t ah[2][4], al[2][4], bb[4][4];
#pragma unroll
                for (int mt = 0; mt < 2; mt++) {
                    LDSM_X4(ah[mt], aoff[mt] + so2);
                    LDSM_X4(al[mt], aoff[mt] + so2 + REG_WORDS * 4);
                }
#pragma unroll
                for (int p = 0; p < 4; p++)
                    LDSM_X4(bb[p], boff[p] + so2 + 2 * REG_WORDS * 4);
#pragma unroll
                for (int nt = 0; nt < 8; nt++) {
                    const uint32_t b0 = bb[nt >> 1][(nt & 1) * 2];
                    const uint32_t b1 = bb[nt >> 1][(nt & 1) * 2 + 1];
#pragma unroll
                    for (int mt = 0; mt < 2; mt++) {
                        mma16(acc[mt][nt], ah[mt], b0, b1);   // hi*hi
                        mma16(acc[mt][nt], al[mt], b0, b1);   // lo*hi
                    }
                }
#pragma unroll
                for (int p = 0; p < 4; p++)
                    LDSM_X4(bb[p], boff[p] + so2 + 3 * REG_WORDS * 4);
#pragma unroll
                for (int nt = 0; nt < 8; nt++) {
                    const uint32_t b0 = bb[nt >> 1][(nt & 1) * 2];
                    const uint32_t b1 = bb[nt >> 1][(nt & 1) * 2 + 1];
#pragma unroll
                    for (int mt = 0; mt < 2; mt++)
                        mma16(acc[mt][nt], ah[mt], b0, b1);   // hi*lo
                }
            }
        }

        // ---- epilogue: masked softmax partials ----
#pragma unroll
        for (int mt = 0; mt < 2; mt++)
#pragma unroll
            for (int rh = 0; rh < 2; rh++) {
                float m = -CUDART_INF_F;
#pragma unroll
                for (int nt = 0; nt < 8; nt++)
#pragma unroll
                    for (int j2 = 0; j2 < 2; j2++) {
                        int tc = t0 + warpN * 64 + nt * 8 + 2 * tig + j2;
                        float x = acc[mt][nt][rh * 2 + j2];
                        m = fmaxf(m, tc < len_b ? x : -CUDART_INF_F);
                    }
                m = fmaxf(m, __shfl_xor_sync(0xffffffffu, m, 1));
                m = fmaxf(m, __shfl_xor_sync(0xffffffffu, m, 2));
                float l = 0.f, w = 0.f;
#pragma unroll
                for (int nt = 0; nt < 8; nt++)
#pragma unroll
                    for (int j2 = 0; j2 < 2; j2++) {
                        int tc = t0 + warpN * 64 + nt * 8 + 2 * tig + j2;
                        if (tc < len_b) {
                            float e = __expf(acc[mt][nt][rh * 2 + j2] - m);
                            l += e;
                            w += e * hs[tc];
                        }
                    }
                l += __shfl_xor_sync(0xffffffffu, l, 1);
                l += __shfl_xor_sync(0xffffffffu, l, 2);
                w += __shfl_xor_sync(0xffffffffu, w, 1);
                w += __shfl_xor_sync(0xffffffffu, w, 2);
                if (tig == 0) {
                    int row = warpM * 32 + mt * 16 + g + rh * 8;
                    part[row * 2 + warpN] = make_float4(m, l, w, 0.f);
                }
            }
        __syncthreads();
        if (tid < 128) {
            float4 r = run[tid];
            float4 p0 = part[tid * 2 + 0];
            float4 p1 = part[tid * 2 + 1];
            float nm = fmaxf(r.x, fmaxf(p0.x, p1.x));
            float er = __expf(r.x - nm);
            float e0 = __expf(p0.x - nm);
            float e1 = __expf(p1.x - nm);
            r.y = r.y * er + p0.y * e0 + p1.y * e1;
            r.z = r.z * er + p0.z * e0 + p1.z * e1;
            r.x = nm;
            run[tid] = r;
        }
        __syncthreads();
    }

    if (tid < 128)
        y_utts[b * V_ + v0 + tid] = run[tid].z / run[tid].y + bsc;
#undef COPY_NEXT
}

// ======================= acts: s2 dot (warp per (b,a)) =====================
__global__ __launch_bounds__(256) void acts_s2_kernel(const float* __restrict__ C_acts,
                                                      const float* __restrict__ c_utt) {
    const int gw = blockIdx.x * 8 + (threadIdx.x >> 5);
    const int lane = threadIdx.x & 31;
    const int b = gw >> 7, a = gw & 127;
    const float4* cr = (const float4*)(C_acts + ((size_t)b * A_ + a) * D_);
    const float4* cu = (const float4*)(c_utt + (size_t)b * D_);
    float s = 0.f;
    for (int i = lane; i < D_ / 4; i += 32) {
        float4 x = cr[i], y = cu[i];
        s += x.x * y.x + x.y * y.y + x.z * y.z + x.w * y.w;
    }
#pragma unroll
    for (int o = 16; o; o >>= 1) s += __shfl_xor_sync(0xffffffffu, s, o);
    if (lane == 0) g_p[gw] = s;
}

// ======================= acts: softmax over a ==============================
__global__ __launch_bounds__(128) void acts_softmax_kernel() {
    __shared__ float w4[4], w4b[4];
    const int b = blockIdx.x;
    const int tid = threadIdx.x;
    const int warp = tid >> 5, lane = tid & 31;
    float s = g_p[b * A_ + tid];
    float m = s;
#pragma unroll
    for (int o = 16; o; o >>= 1) m = fmaxf(m, __shfl_xor_sync(0xffffffffu, m, o));
    if (lane == 0) w4[warp] = m;
    __syncthreads();
    m = fmaxf(fmaxf(w4[0], w4[1]), fmaxf(w4[2], w4[3]));
    float e = __expf(s - m);
    float smv = e;
#pragma unroll
    for (int o = 16; o; o >>= 1) smv += __shfl_xor_sync(0xffffffffu, smv, o);
    if (lane == 0) w4b[warp] = smv;
    __syncthreads();
    float tot = w4b[0] + w4b[1] + w4b[2] + w4b[3];
    g_p[b * A_ + tid] = e / tot;
}

// ======================= acts phase B: q = p @ C_acts ======================
__global__ __launch_bounds__(128) void acts_q_kernel(const float* __restrict__ C_acts) {
    __shared__ float p[A_];
    const int b = blockIdx.y;
    const int d = blockIdx.x * 100 + threadIdx.x;
    if (threadIdx.x < A_) p[threadIdx.x] = g_p[b * A_ + threadIdx.x];
    __syncthreads();
    if (threadIdx.x >= 100) return;
    const float* Cb = C_acts + (size_t)b * A_ * D_ + d;
    float q = 0.f;
#pragma unroll 4
    for (int a = 0; a < A_; a++) q = fmaf(p[a], Cb[(size_t)a * D_], q);
    g_q[b * D_ + d] = q;
}

// ======================= y_acts: warp per v-row ============================
__global__ __launch_bounds__(256) void yacts_kernel(const float* __restrict__ vals,
                                                    float* __restrict__ y_acts) {
    __shared__ float qs[16 * D_];
    const int tid = threadIdx.x, lane = tid & 31, wid = tid >> 5;
    const int b0 = blockIdx.y * 16;
    const int v = blockIdx.x * 8 + wid;

    for (int f = tid; f < 16 * D_; f += 256) qs[f] = g_q[b0 * D_ + f];
    __syncthreads();

    float acc[16];
#pragma unroll
    for (int bb = 0; bb < 16; bb++) acc[bb] = 0.f;

    const float4* vr = (const float4*)(vals + (size_t)v * D_);
    const float4* q4 = (const float4*)qs;
    for (int d4 = lane; d4 < D_ / 4; d4 += 32) {
        float4 r = vr[d4];
#pragma unroll
        for (int bb = 0; bb < 16; bb++) {
            float4 q = q4[bb * (D_ / 4) + d4];
            acc[bb] += r.x * q.x + r.y * q.y + r.z * q.z + r.w * q.w;
        }
    }
#pragma unroll
    for (int o = 16; o; o >>= 1)
#pragma unroll
        for (int bb = 0; bb < 16; bb++)
            acc[bb] += __shfl_xor_sync(0xffffffffu, acc[bb], o);
    if (lane == 0) {
#pragma unroll
        for (int bb = 0; bb < 16; bb++)
            y_acts[(size_t)(b0 + bb) * V_ + v] = acc[bb];
    }
}

// ===========================================================================
extern "C" void kernel_launch(void* const* d_in, const int* in_sizes, int n_in,
                              void* d_out, int out_size) {
    const float* H       = (const float*)d_in[0];
    const float* c_utt   = (const float*)d_in[1];
    const float* C_acts  = (const float*)d_in[2];
    const float* C_vals  = (const float*)d_in[3];
    const float* W       = (const float*)d_in[4];
    const float* b_score = (const float*)d_in[5];
    const int*   lens    = (const int*)d_in[6];

    float* y_utts = (float*)d_out;
    float* y_acts = (float*)d_out + (size_t)B_ * V_;

    static bool init = false;
    if (!init) {
        init = true;
        cudaFuncSetAttribute(fused_kernel,
                             cudaFuncAttributeMaxDynamicSharedMemorySize, SMEM_BYTES);
    }

    prep_h_kernel<<<(B_ * T_) / 8, 256>>>(H, W, lens);
    split_v_kernel<<<V_ / 8, 256>>>(C_vals);
    fused_kernel<<<dim3(V_ / 128, B_), 256, SMEM_BYTES>>>(lens, b_score, y_utts);
    acts_s2_kernel<<<B_ * A_ / 8, 256>>>(C_acts, c_utt);
    acts_softmax_kernel<<<B_, 128>>>();
    acts_q_kernel<<<dim3(4, B_), 128>>>(C_acts);
    yacts_kernel<<<dim3(V_ / 8, B_ / 16), 256>>>(C_vals, y_acts);
}

// round 9
// speedup vs baseline: 2.7561x; 1.0601x over previous
#include <cuda_runtime.h>
#include <cuda_bf16.h>
#include <math_constants.h>
#include <stdint.h>

#define B_ 128
#define T_ 512
#define D_ 400
#define DP_ 416                 // padded K (pad is zero-initialized, never written)
#define V_ 1024
#define A_ 128

#define KC      32              // K elems per chunk (two m16n8k16 steps)
#define NCHUNK  13              // 13*32 = 416
#define STRIDEW 20              // words per row (16 data + 4 pad), conflict-free
#define REG_WORDS   (128 * STRIDEW)
#define STAGE_WORDS (4 * REG_WORDS)     // Ahi, Alo, Bhi, Blo
#define STAGE_BYTES (STAGE_WORDS * 4)   // 40960
#define NSTAGE 2
#define SMEM_WORDS  (NSTAGE * STAGE_WORDS + 512 + 1024 + 512)
#define SMEM_BYTES  (SMEM_WORDS * 4)    // 90112

// -------- scratch (device globals; zero-initialized at load) ---------------
__device__ __align__(256) __nv_bfloat16 g_Hhi[B_ * T_ * DP_];
__device__ __align__(256) __nv_bfloat16 g_Hlo[B_ * T_ * DP_];
__device__ __align__(256) __nv_bfloat16 g_Vhi[V_ * DP_];
__device__ __align__(256) __nv_bfloat16 g_Vlo[V_ * DP_];
__device__ float g_hW[B_ * T_];
__device__ float g_p[B_ * A_];
__device__ float g_q[B_ * D_];

// ======================= helpers ===========================================
__device__ __forceinline__ uint32_t smem_u32(const void* p) {
    uint32_t a;
    asm("{ .reg .u64 t; cvta.to.shared.u64 t, %1; cvt.u32.u64 %0, t; }"
        : "=r"(a) : "l"(p));
    return a;
}
#define CP_ASYNC16(dst, src) \
    asm volatile("cp.async.cg.shared.global [%0], [%1], 16;" \
                 :: "r"(dst), "l"(src) : "memory")
#define CP_COMMIT() asm volatile("cp.async.commit_group;" ::: "memory")
#define CP_WAIT0()  asm volatile("cp.async.wait_group 0;" ::: "memory")

#define LDSM_X4(R, addr)                                                      \
    asm volatile("ldmatrix.sync.aligned.m8n8.x4.shared.b16 {%0,%1,%2,%3}, [%4];" \
        : "=r"((R)[0]), "=r"((R)[1]), "=r"((R)[2]), "=r"((R)[3]) : "r"(addr))

__device__ __forceinline__ void mma16(float d[4], const uint32_t a[4],
                                      const uint32_t b0, const uint32_t b1) {
    asm volatile(
        "mma.sync.aligned.m16n8k16.row.col.f32.bf16.bf16.f32 "
        "{%0,%1,%2,%3}, {%4,%5,%6,%7}, {%8,%9}, {%0,%1,%2,%3};"
        : "+f"(d[0]), "+f"(d[1]), "+f"(d[2]), "+f"(d[3])
        : "r"(a[0]), "r"(a[1]), "r"(a[2]), "r"(a[3]), "r"(b0), "r"(b1));
}

// ============ prep: H -> bf16 hi/lo split AND hW = H.W (warp per row) ======
__global__ __launch_bounds__(256) void prep_h_kernel(const float* __restrict__ H,
                                                     const float* __restrict__ W,
                                                     const int* __restrict__ lens) {
    __shared__ float sW[D_];
    for (int d = threadIdx.x; d < D_; d += 256) sW[d] = W[d];
    __syncthreads();

    const int wid = threadIdx.x >> 5, lane = threadIdx.x & 31;
    const size_t row = (size_t)blockIdx.x * 8 + wid;
    const int t = (int)(row & (T_ - 1));
    const int b = (int)(row >> 9);
    if (t >= lens[b]) return;                 // whole warp exits together

    const float* src = H + row * D_;
    float s = 0.f;
    for (int d4 = lane; d4 < D_ / 4; d4 += 32) {
        float4 x = ((const float4*)src)[d4];
        __nv_bfloat16 h[4], l[4];
        h[0] = __float2bfloat16_rn(x.x); l[0] = __float2bfloat16_rn(x.x - __bfloat162float(h[0]));
        h[1] = __float2bfloat16_rn(x.y); l[1] = __float2bfloat16_rn(x.y - __bfloat162float(h[1]));
        h[2] = __float2bfloat16_rn(x.z); l[2] = __float2bfloat16_rn(x.z - __bfloat162float(h[2]));
        h[3] = __float2bfloat16_rn(x.w); l[3] = __float2bfloat16_rn(x.w - __bfloat162float(h[3]));
        *(uint2*)(g_Hhi + row * DP_ + d4 * 4) = *(const uint2*)h;
        *(uint2*)(g_Hlo + row * DP_ + d4 * 4) = *(const uint2*)l;
        const float* w = sW + d4 * 4;
        s += x.x * w[0] + x.y * w[1] + x.z * w[2] + x.w * w[3];
    }
#pragma unroll
    for (int o = 16; o; o >>= 1) s += __shfl_xor_sync(0xffffffffu, s, o);
    if (lane == 0) g_hW[row] = s;
}

// ======================= V: bf16 hi/lo split (warp per row) ================
__global__ __launch_bounds__(256) void split_v_kernel(const float* __restrict__ src) {
    const int wid = threadIdx.x >> 5, lane = threadIdx.x & 31;
    const size_t v = (size_t)blockIdx.x * 8 + wid;
    const float* s = src + v * D_;
    for (int d4 = lane; d4 < D_ / 4; d4 += 32) {
        float4 x = ((const float4*)s)[d4];
        __nv_bfloat16 h[4], l[4];
        h[0] = __float2bfloat16_rn(x.x); l[0] = __float2bfloat16_rn(x.x - __bfloat162float(h[0]));
        h[1] = __float2bfloat16_rn(x.y); l[1] = __float2bfloat16_rn(x.y - __bfloat162float(h[1]));
        h[2] = __float2bfloat16_rn(x.z); l[2] = __float2bfloat16_rn(x.z - __bfloat162float(h[2]));
        h[3] = __float2bfloat16_rn(x.w); l[3] = __float2bfloat16_rn(x.w - __bfloat162float(h[3]));
        *(uint2*)(g_Vhi + v * DP_ + d4 * 4) = *(const uint2*)h;
        *(uint2*)(g_Vlo + v * DP_ + d4 * 4) = *(const uint2*)l;
    }
}

// ======================= fused scores GEMM + softmax =======================
__global__ __launch_bounds__(256, 2) void fused_kernel(const int* __restrict__ lens,
                                                       const float* __restrict__ b_score,
                                                       float* __restrict__ y_utts) {
    extern __shared__ float sm[];
    float* hs = sm + NSTAGE * STAGE_WORDS;               // 512
    float4* part = (float4*)(hs + 512);                  // 256 float4
    float4* run  = part + 256;                           // 128 float4
    const uint32_t sbase = smem_u32(sm);

    const int tid = threadIdx.x, lane = tid & 31, wid = tid >> 5;
    const int g = lane >> 2, tig = lane & 3;
    const int warpM = wid & 3, warpN = wid >> 2;
    const int b = blockIdx.y, v0 = blockIdx.x * 128;
    const int len_b = lens[b];
    const float bsc = b_score[0];
    const int n_tiles = (len_b + 127) >> 7;
    const int total_c = n_tiles * NCHUNK;

    for (int i = tid; i < T_; i += 256) hs[i] = g_hW[b * T_ + i];
    if (tid < 128) run[tid] = make_float4(-CUDART_INF_F, 0.f, 0.f, 0.f);
    __syncthreads();

    // ---- per-thread copy sources: 2 threads/row, each covers 16 elems ----
    const int crow = tid >> 1, ch = tid & 1;
    const __nv_bfloat16* pAh = g_Vhi + (size_t)(v0 + crow) * DP_ + ch * 16;
    const __nv_bfloat16* pAl = g_Vlo + (size_t)(v0 + crow) * DP_ + ch * 16;
    const __nv_bfloat16* pBh = g_Hhi + (size_t)(b * T_ + crow) * DP_ + ch * 16;
    const __nv_bfloat16* pBl = g_Hlo + (size_t)(b * T_ + crow) * DP_ + ch * 16;
    const uint32_t dst0 = sbase + (crow * STRIDEW + ch * 8) * 4;

    int cp_t = 0, cp_k = 0;
#define COPY_NEXT(ST) do {                                                     \
        uint32_t _d = dst0 + (ST) * STAGE_BYTES;                               \
        size_t _o = (size_t)cp_t * DP_ + cp_k;                                 \
        CP_ASYNC16(_d,                          pAh + cp_k);                   \
        CP_ASYNC16(_d + 16,                     pAh + cp_k + 8);               \
        CP_ASYNC16(_d + REG_WORDS * 4,          pAl + cp_k);                   \
        CP_ASYNC16(_d + REG_WORDS * 4 + 16,     pAl + cp_k + 8);               \
        CP_ASYNC16(_d + 2 * REG_WORDS * 4,      pBh + _o);                     \
        CP_ASYNC16(_d + 2 * REG_WORDS * 4 + 16, pBh + _o + 8);                 \
        CP_ASYNC16(_d + 3 * REG_WORDS * 4,      pBl + _o);                     \
        CP_ASYNC16(_d + 3 * REG_WORDS * 4 + 16, pBl + _o + 8);                 \
        cp_k += KC; if (cp_k == DP_) { cp_k = 0; cp_t += 128; }                \
    } while (0)

    // ---- ldmatrix per-thread offsets ----
    const int arow = lane & 15;
    const int acol = (lane >> 4) * 4;
    uint32_t aoff[2];
#pragma unroll
    for (int mt = 0; mt < 2; mt++)
        aoff[mt] = sbase + ((warpM * 32 + mt * 16 + arow) * STRIDEW + acol) * 4;
    const int brow = (lane & 7) + ((lane >> 4) & 1) * 8;
    const int bcol = ((lane >> 3) & 1) * 4;
    uint32_t boff[4];
#pragma unroll
    for (int p = 0; p < 4; p++)
        boff[p] = sbase + ((warpN * 64 + p * 16 + brow) * STRIDEW + bcol) * 4;

    COPY_NEXT(0); CP_COMMIT();

    int fc = 0;
    for (int tt = 0; tt < n_tiles; tt++) {
        const int t0 = tt * 128;

        float acc[2][8][4];
#pragma unroll
        for (int mt = 0; mt < 2; mt++)
#pragma unroll
            for (int nt = 0; nt < 8; nt++)
#pragma unroll
                for (int r = 0; r < 4; r++) acc[mt][nt][r] = 0.f;

        for (int kc = 0; kc < NCHUNK; kc++, fc++) {
            CP_WAIT0();                       // chunk fc landed (this thread)
            __syncthreads();                  // published to all; prev stage free
            if (fc + 1 < total_c) COPY_NEXT((fc + 1) & 1);
            CP_COMMIT();

            const uint32_t so = (fc & 1) * STAGE_BYTES;
#pragma unroll
            for (int s = 0; s < 2; s++) {
                const uint32_t so2 = so + s * 32;     // +8 words per k-step
                uint32_t ah[2][4], al[2][4], bb[4][4];
#pragma unroll
                for (int mt = 0; mt < 2; mt++) {
                    LDSM_X4(ah[mt], aoff[mt] + so2);
                    LDSM_X4(al[mt], aoff[mt] + so2 + REG_WORDS * 4);
                }
#pragma unroll
                for (int p = 0; p < 4; p++)
                    LDSM_X4(bb[p], boff[p] + so2 + 2 * REG_WORDS * 4);
                // ---- pass 1: hi*hi (16 independent accumulators) ----
#pragma unroll
                for (int nt = 0; nt < 8; nt++) {
                    const uint32_t b0 = bb[nt >> 1][(nt & 1) * 2];
                    const uint32_t b1 = bb[nt >> 1][(nt & 1) * 2 + 1];
#pragma unroll
                    for (int mt = 0; mt < 2; mt++)
                        mma16(acc[mt][nt], ah[mt], b0, b1);
                }
                // ---- pass 2: lo*hi (RAW distance 16) ----
#pragma unroll
                for (int nt = 0; nt < 8; nt++) {
                    const uint32_t b0 = bb[nt >> 1][(nt & 1) * 2];
                    const uint32_t b1 = bb[nt >> 1][(nt & 1) * 2 + 1];
#pragma unroll
                    for (int mt = 0; mt < 2; mt++)
                        mma16(acc[mt][nt], al[mt], b0, b1);
                }
                // ---- pass 3: hi*lo ----
#pragma unroll
                for (int p = 0; p < 4; p++)
                    LDSM_X4(bb[p], boff[p] + so2 + 3 * REG_WORDS * 4);
#pragma unroll
                for (int nt = 0; nt < 8; nt++) {
                    const uint32_t b0 = bb[nt >> 1][(nt & 1) * 2];
                    const uint32_t b1 = bb[nt >> 1][(nt & 1) * 2 + 1];
#pragma unroll
                    for (int mt = 0; mt < 2; mt++)
                        mma16(acc[mt][nt], ah[mt], b0, b1);
                }
            }
        }

        // ---- epilogue: masked softmax partials ----
#pragma unroll
        for (int mt = 0; mt < 2; mt++)
#pragma unroll
            for (int rh = 0; rh < 2; rh++) {
                float m = -CUDART_INF_F;
#pragma unroll
                for (int nt = 0; nt < 8; nt++)
#pragma unroll
                    for (int j2 = 0; j2 < 2; j2++) {
                        int tc = t0 + warpN * 64 + nt * 8 + 2 * tig + j2;
                        float x = acc[mt][nt][rh * 2 + j2];
                        m = fmaxf(m, tc < len_b ? x : -CUDART_INF_F);
                    }
                m = fmaxf(m, __shfl_xor_sync(0xffffffffu, m, 1));
                m = fmaxf(m, __shfl_xor_sync(0xffffffffu, m, 2));
                float l = 0.f, w = 0.f;
#pragma unroll
                for (int nt = 0; nt < 8; nt++)
#pragma unroll
                    for (int j2 = 0; j2 < 2; j2++) {
                        int tc = t0 + warpN * 64 + nt * 8 + 2 * tig + j2;
                        if (tc < len_b) {
                            float e = __expf(acc[mt][nt][rh * 2 + j2] - m);
                            l += e;
                            w += e * hs[tc];
                        }
                    }
                l += __shfl_xor_sync(0xffffffffu, l, 1);
                l += __shfl_xor_sync(0xffffffffu, l, 2);
                w += __shfl_xor_sync(0xffffffffu, w, 1);
                w += __shfl_xor_sync(0xffffffffu, w, 2);
                if (tig == 0) {
                    int row = warpM * 32 + mt * 16 + g + rh * 8;
                    part[row * 2 + warpN] = make_float4(m, l, w, 0.f);
                }
            }
        __syncthreads();
        if (tid < 128) {
            float4 r = run[tid];
            float4 p0 = part[tid * 2 + 0];
            float4 p1 = part[tid * 2 + 1];
            float nm = fmaxf(r.x, fmaxf(p0.x, p1.x));
            float er = __expf(r.x - nm);
            float e0 = __expf(p0.x - nm);
            float e1 = __expf(p1.x - nm);
            r.y = r.y * er + p0.y * e0 + p1.y * e1;
            r.z = r.z * er + p0.z * e0 + p1.z * e1;
            r.x = nm;
            run[tid] = r;
        }
        __syncthreads();
    }

    if (tid < 128)
        y_utts[b * V_ + v0 + tid] = run[tid].z / run[tid].y + bsc;
#undef COPY_NEXT
}

// ======================= acts: s2 dot (warp per (b,a)) =====================
__global__ __launch_bounds__(256) void acts_s2_kernel(const float* __restrict__ C_acts,
                                                      const float* __restrict__ c_utt) {
    const int gw = blockIdx.x * 8 + (threadIdx.x >> 5);
    const int lane = threadIdx.x & 31;
    const int b = gw >> 7, a = gw & 127;
    const float4* cr = (const float4*)(C_acts + ((size_t)b * A_ + a) * D_);
    const float4* cu = (const float4*)(c_utt + (size_t)b * D_);
    float s = 0.f;
    for (int i = lane; i < D_ / 4; i += 32) {
        float4 x = cr[i], y = cu[i];
        s += x.x * y.x + x.y * y.y + x.z * y.z + x.w * y.w;
    }
#pragma unroll
    for (int o = 16; o; o >>= 1) s += __shfl_xor_sync(0xffffffffu, s, o);
    if (lane == 0) g_p[gw] = s;
}

// ======================= acts: softmax over a ==============================
__global__ __launch_bounds__(128) void acts_softmax_kernel() {
    __shared__ float w4[4], w4b[4];
    const int b = blockIdx.x;
    const int tid = threadIdx.x;
    const int warp = tid >> 5, lane = tid & 31;
    float s = g_p[b * A_ + tid];
    float m = s;
#pragma unroll
    for (int o = 16; o; o >>= 1) m = fmaxf(m, __shfl_xor_sync(0xffffffffu, m, o));
    if (lane == 0) w4[warp] = m;
    __syncthreads();
    m = fmaxf(fmaxf(w4[0], w4[1]), fmaxf(w4[2], w4[3]));
    float e = __expf(s - m);
    float smv = e;
#pragma unroll
    for (int o = 16; o; o >>= 1) smv += __shfl_xor_sync(0xffffffffu, smv, o);
    if (lane == 0) w4b[warp] = smv;
    __syncthreads();
    float tot = w4b[0] + w4b[1] + w4b[2] + w4b[3];
    g_p[b * A_ + tid] = e / tot;
}

// ======================= acts phase B: q = p @ C_acts ======================
__global__ __launch_bounds__(128) void acts_q_kernel(const float* __restrict__ C_acts) {
    __shared__ float p[A_];
    const int b = blockIdx.y;
    const int d = blockIdx.x * 100 + threadIdx.x;
    if (threadIdx.x < A_) p[threadIdx.x] = g_p[b * A_ + threadIdx.x];
    __syncthreads();
    if (threadIdx.x >= 100) return;
    const float* Cb = C_acts + (size_t)b * A_ * D_ + d;
    float q = 0.f;
#pragma unroll 4
    for (int a = 0; a < A_; a++) q = fmaf(p[a], Cb[(size_t)a * D_], q);
    g_q[b * D_ + d] = q;
}

// ======================= y_acts: warp per v-row ============================
__global__ __launch_bounds__(256) void yacts_kernel(const float* __restrict__ vals,
                                                    float* __restrict__ y_acts) {
    __shared__ float qs[16 * D_];
    const int tid = threadIdx.x, lane = tid & 31, wid = tid >> 5;
    const int b0 = blockIdx.y * 16;
    const int v = blockIdx.x * 8 + wid;

    for (int f = tid; f < 16 * D_; f += 256) qs[f] = g_q[b0 * D_ + f];
    __syncthreads();

    float acc[16];
#pragma unroll
    for (int bb = 0; bb < 16; bb++) acc[bb] = 0.f;

    const float4* vr = (const float4*)(vals + (size_t)v * D_);
    const float4* q4 = (const float4*)qs;
    for (int d4 = lane; d4 < D_ / 4; d4 += 32) {
        float4 r = vr[d4];
#pragma unroll
        for (int bb = 0; bb < 16; bb++) {
            float4 q = q4[bb * (D_ / 4) + d4];
            acc[bb] += r.x * q.x + r.y * q.y + r.z * q.z + r.w * q.w;
        }
    }
#pragma unroll
    for (int o = 16; o; o >>= 1)
#pragma unroll
        for (int bb = 0; bb < 16; bb++)
            acc[bb] += __shfl_xor_sync(0xffffffffu, acc[bb], o);
    if (lane == 0) {
#pragma unroll
        for (int bb = 0; bb < 16; bb++)
            y_acts[(size_t)(b0 + bb) * V_ + v] = acc[bb];
    }
}

// ===========================================================================
extern "C" void kernel_launch(void* const* d_in, const int* in_sizes, int n_in,
                              void* d_out, int out_size) {
    const float* H       = (const float*)d_in[0];
    const float* c_utt   = (const float*)d_in[1];
    const float* C_acts  = (const float*)d_in[2];
    const float* C_vals  = (const float*)d_in[3];
    const float* W       = (const float*)d_in[4];
    const float* b_score = (const float*)d_in[5];
    const int*   lens    = (const int*)d_in[6];

    float* y_utts = (float*)d_out;
    float* y_acts = (float*)d_out + (size_t)B_ * V_;

    static cudaStream_t s_side = nullptr;
    static cudaEvent_t ev_fork = nullptr, ev_join = nullptr;
    if (!s_side) {
        cudaStreamCreateWithFlags(&s_side, cudaStreamNonBlocking);
        cudaEventCreateWithFlags(&ev_fork, cudaEventDisableTiming);
        cudaEventCreateWithFlags(&ev_join, cudaEventDisableTiming);
        cudaFuncSetAttribute(fused_kernel,
                             cudaFuncAttributeMaxDynamicSharedMemorySize, SMEM_BYTES);
    }

    // fork: acts chain runs concurrently with prep + fused
    cudaEventRecord(ev_fork, 0);
    cudaStreamWaitEvent(s_side, ev_fork, 0);

    prep_h_kernel<<<(B_ * T_) / 8, 256>>>(H, W, lens);
    split_v_kernel<<<V_ / 8, 256>>>(C_vals);
    fused_kernel<<<dim3(V_ / 128, B_), 256, SMEM_BYTES>>>(lens, b_score, y_utts);

    acts_s2_kernel<<<B_ * A_ / 8, 256, 0, s_side>>>(C_acts, c_utt);
    acts_softmax_kernel<<<B_, 128, 0, s_side>>>();
    acts_q_kernel<<<dim3(4, B_), 128, 0, s_side>>>(C_acts);
    yacts_kernel<<<dim3(V_ / 8, B_ / 16), 256, 0, s_side>>>(C_vals, y_acts);

    // join
    cudaEventRecord(ev_join, s_side);
    cudaStreamWaitEvent(0, ev_join, 0);
}